// round 10
// baseline (speedup 1.0000x reference)
#include <cuda_runtime.h>
#include <cuda_bf16.h>
#include <math.h>
#include <stdint.h>

// Problem constants
#define BB 4
#define TT 2048
#define CC 1024
#define HH 16
#define DD 64
#define MM (BB * TT)         // 8192
#define N_QKV (3 * CC)       // 3072
#define ATTN_SCALE 0.12f
#define RMS_EPS 1e-6f

// ---------------- device scratch (allocation-free) ----------------
__device__ float g_qkv[(size_t)MM * N_QKV];          // (M, 3C)
__device__ __nv_bfloat16 g_xh[(size_t)MM * CC],     g_xl[(size_t)MM * CC];
__device__ __nv_bfloat16 g_wh[(size_t)N_QKV * CC],  g_wl[(size_t)N_QKV * CC];
__device__ __nv_bfloat16 g_yh[(size_t)MM * CC],     g_yl[(size_t)MM * CC];
__device__ __nv_bfloat16 g_ph[(size_t)CC * CC],     g_pl[(size_t)CC * CC];
#define AHD ((size_t)BB * HH * TT * DD)
__device__ __nv_bfloat16 g_qh[AHD], g_ql[AHD];
__device__ __nv_bfloat16 g_kh[AHD], g_kl[AHD];
__device__ __nv_bfloat16 g_vh[AHD], g_vl[AHD];
__device__ __nv_bfloat16 g_vth[AHD], g_vtl[AHD];

// =================================================================
// common helpers
// =================================================================
__device__ __forceinline__ uint32_t smem_u32(const void* p) {
    uint32_t a;
    asm("{ .reg .u64 t; cvta.to.shared.u64 t, %1; cvt.u32.u64 %0, t; }"
        : "=r"(a) : "l"(p));
    return a;
}

__device__ __forceinline__ void mma16816(float* d, const uint32_t* a, const uint32_t* b) {
    asm volatile(
        "mma.sync.aligned.m16n8k16.row.col.f32.bf16.bf16.f32 "
        "{%0,%1,%2,%3}, {%4,%5,%6,%7}, {%8,%9}, {%0,%1,%2,%3};"
        : "+f"(d[0]), "+f"(d[1]), "+f"(d[2]), "+f"(d[3])
        : "r"(a[0]), "r"(a[1]), "r"(a[2]), "r"(a[3]), "r"(b[0]), "r"(b[1]));
}

#define LDSM_X4(r, addr) \
    asm volatile("ldmatrix.sync.aligned.m8n8.x4.shared.b16 {%0,%1,%2,%3}, [%4];" \
                 : "=r"((r)[0]), "=r"((r)[1]), "=r"((r)[2]), "=r"((r)[3]) : "r"(addr))
#define LDSM_X2(r, addr) \
    asm volatile("ldmatrix.sync.aligned.m8n8.x2.shared.b16 {%0,%1}, [%2];" \
                 : "=r"((r)[0]), "=r"((r)[1]) : "r"(addr))

#define CP_ASYNC(dst, src) \
    asm volatile("cp.async.cg.shared.global [%0], [%1], 16;" \
                 :: "r"(dst), "l"(src) : "memory")
#define CP_COMMIT() asm volatile("cp.async.commit_group;" ::: "memory")
#define CP_WAIT1()  asm volatile("cp.async.wait_group 1;" ::: "memory")

__device__ __forceinline__ uint32_t pack_bf16(float a, float b) {
    __nv_bfloat16 ha = __float2bfloat16(a);
    __nv_bfloat16 hb = __float2bfloat16(b);
    return (uint32_t)__bfloat16_as_ushort(ha) |
           ((uint32_t)__bfloat16_as_ushort(hb) << 16);
}

// =================================================================
// split: fp32 -> bf16 hi + bf16 lo (residual)
// =================================================================
__global__ __launch_bounds__(256)
void split_bf16(const float* __restrict__ in,
                __nv_bfloat16* __restrict__ hi, __nv_bfloat16* __restrict__ lo,
                int n)
{
    const int i = (blockIdx.x * 256 + threadIdx.x) * 4;
    if (i >= n) return;
    float4 f4 = *(const float4*)(in + i);
    float f[4] = {f4.x, f4.y, f4.z, f4.w};
    uint16_t h[4], l[4];
#pragma unroll
    for (int j = 0; j < 4; j++) {
        __nv_bfloat16 hb = __float2bfloat16(f[j]);
        __nv_bfloat16 lb = __float2bfloat16(f[j] - __bfloat162float(hb));
        h[j] = __bfloat16_as_ushort(hb);
        l[j] = __bfloat16_as_ushort(lb);
    }
    *(uint2*)(hi + i) = make_uint2((uint32_t)h[0] | ((uint32_t)h[1] << 16),
                                   (uint32_t)h[2] | ((uint32_t)h[3] << 16));
    *(uint2*)(lo + i) = make_uint2((uint32_t)l[0] | ((uint32_t)l[1] << 16),
                                   (uint32_t)l[2] | ((uint32_t)l[3] << 16));
}

// =================================================================
// mma.sync bf16x3 GEMM (pre-split, cp.async double buffer, ldmatrix)
// =================================================================
#define SROW 20
#define ARR_W (128 * SROW)
#define BUF_W (4 * ARR_W)
#define GEMM_SMEM (2 * BUF_W * 4)

__global__ __launch_bounds__(256, 2)
void mma_gemm_pre(const __nv_bfloat16* __restrict__ Ahg,
                  const __nv_bfloat16* __restrict__ Alg,
                  const __nv_bfloat16* __restrict__ Bhg,
                  const __nv_bfloat16* __restrict__ Blg,
                  float* __restrict__ C, int M, int N, int K)
{
    extern __shared__ uint32_t sw[];
    const uint32_t sbase = smem_u32(sw);

    const int tid = threadIdx.x;
    const int wid = tid >> 5;
    const int lane = tid & 31;
    const int g = lane >> 2;
    const int tig = lane & 3;
    const int wm = (wid & 1) * 64;
    const int wn = (wid >> 1) * 32;

    const int bm = blockIdx.y * 128;
    const int bn = blockIdx.x * 128;

    const int s0 = tid * 2;
    const int lrow0 = s0 >> 2, lseg0 = s0 & 3;
    const int lrow1 = (s0 + 1) >> 2, lseg1 = (s0 + 1) & 3;

    const uint32_t a16 = ((uint32_t)((wm + (lane & 15)) * SROW + (lane >> 4) * 4)) * 4;
    const uint32_t b8  = ((uint32_t)((wn + (lane & 7)) * SROW + ((lane >> 3) & 1) * 4)) * 4;

    float acc[4][4][4];
#pragma unroll
    for (int mt = 0; mt < 4; mt++)
#pragma unroll
        for (int nt = 0; nt < 4; nt++)
#pragma unroll
            for (int r = 0; r < 4; r++) acc[mt][nt][r] = 0.0f;

    const int nch = K >> 5;

    auto issue = [&](int ci, int buf) {
        const int kc = ci << 5;
        const uint32_t bb = sbase + buf * (BUF_W * 4);
#pragma unroll
        for (int j = 0; j < 2; j++) {
            const int row = j ? lrow1 : lrow0;
            const int seg = j ? lseg1 : lseg0;
            const size_t goff = (size_t)(bm + row) * K + kc + seg * 8;
            const size_t goffB = (size_t)(bn + row) * K + kc + seg * 8;
            const uint32_t soff = (row * SROW + seg * 4) * 4;
            CP_ASYNC(bb + 0 * ARR_W * 4 + soff, Ahg + goff);
            CP_ASYNC(bb + 1 * ARR_W * 4 + soff, Alg + goff);
            CP_ASYNC(bb + 2 * ARR_W * 4 + soff, Bhg + goffB);
            CP_ASYNC(bb + 3 * ARR_W * 4 + soff, Blg + goffB);
        }
    };

    issue(0, 0); CP_COMMIT();
    issue(1, 1); CP_COMMIT();

    for (int ci = 0; ci < nch; ci++) {
        const int buf = ci & 1;
        CP_WAIT1();
        __syncthreads();

        const uint32_t Ah_b = sbase + buf * (BUF_W * 4);
        const uint32_t Al_b = Ah_b + ARR_W * 4;
        const uint32_t Bh_b = Ah_b + 2 * ARR_W * 4;
        const uint32_t Bl_b = Ah_b + 3 * ARR_W * 4;

#pragma unroll
        for (int ks = 0; ks < 2; ks++) {
            const uint32_t kwb = ks * 32;
            uint32_t bhf[4][2], blf[4][2];
#pragma unroll
            for (int nt = 0; nt < 4; nt++) {
                LDSM_X2(bhf[nt], Bh_b + b8 + nt * (8 * SROW * 4) + kwb);
                LDSM_X2(blf[nt], Bl_b + b8 + nt * (8 * SROW * 4) + kwb);
            }
#pragma unroll
            for (int mt = 0; mt < 4; mt++) {
                uint32_t ah[4], al[4];
                LDSM_X4(ah, Ah_b + a16 + mt * (16 * SROW * 4) + kwb);
                LDSM_X4(al, Al_b + a16 + mt * (16 * SROW * 4) + kwb);
#pragma unroll
                for (int nt = 0; nt < 4; nt++) {
                    mma16816(acc[mt][nt], ah, bhf[nt]);
                    mma16816(acc[mt][nt], ah, blf[nt]);
                    mma16816(acc[mt][nt], al, bhf[nt]);
                }
            }
        }
        __syncthreads();
        if (ci + 2 < nch) issue(ci + 2, buf);
        CP_COMMIT();
    }

#pragma unroll
    for (int mt = 0; mt < 4; mt++) {
        const int r0 = bm + wm + mt * 16 + g;
#pragma unroll
        for (int nt = 0; nt < 4; nt++) {
            const int col = bn + wn + nt * 8 + tig * 2;
            *(float2*)&C[(size_t)r0 * N + col] =
                make_float2(acc[mt][nt][0], acc[mt][nt][1]);
            *(float2*)&C[(size_t)(r0 + 8) * N + col] =
                make_float2(acc[mt][nt][2], acc[mt][nt][3]);
        }
    }
}

// =================================================================
// Post-process: v-mix, rmsnorm, rotary; q pre-scaled by ATTN_SCALE;
// outputs bf16 hi/lo q,k,v in (B*H, T, D) layout.
// =================================================================
__device__ __forceinline__ void split_store(__nv_bfloat16* H, __nv_bfloat16* L,
                                            size_t o, float f) {
    __nv_bfloat16 hb = __float2bfloat16(f);
    H[o] = hb;
    L[o] = __float2bfloat16(f - __bfloat162float(hb));
}

__global__ __launch_bounds__(256)
void postproc(const float* __restrict__ qkv, const float* __restrict__ ve,
              const float* __restrict__ lambdas,
              __nv_bfloat16* __restrict__ qh, __nv_bfloat16* __restrict__ ql,
              __nv_bfloat16* __restrict__ kh, __nv_bfloat16* __restrict__ kl,
              __nv_bfloat16* __restrict__ vh, __nv_bfloat16* __restrict__ vl)
{
    const int pair = blockIdx.x * 8 + (threadIdx.x >> 5);
    const int l = threadIdx.x & 31;
    const int m = pair >> 4;
    const int h = pair & 15;
    const int t = m & (TT - 1);
    const int b = m >> 11;

    const float* row = qkv + (size_t)m * N_QKV + h * DD;
    float q0 = row[l],          q1 = row[l + 32];
    float k0 = row[CC + l],     k1 = row[CC + l + 32];
    float v0 = row[2 * CC + l], v1 = row[2 * CC + l + 32];

    const float lam0 = lambdas[0], lam1 = lambdas[1];
    const float* verow = ve + (size_t)m * CC + h * DD;
    v0 = lam0 * v0 + lam1 * verow[l];
    v1 = lam0 * v1 + lam1 * verow[l + 32];

    float sq = q0 * q0 + q1 * q1;
    float sk = k0 * k0 + k1 * k1;
#pragma unroll
    for (int o = 16; o; o >>= 1) {
        sq += __shfl_xor_sync(0xffffffffu, sq, o);
        sk += __shfl_xor_sync(0xffffffffu, sk, o);
    }
    float rq = 1.0f / sqrtf(sq * (1.0f / 64.0f) + RMS_EPS);
    float rk = 1.0f / sqrtf(sk * (1.0f / 64.0f) + RMS_EPS);
    q0 *= rq; q1 *= rq;
    k0 *= rk; k1 *= rk;

    float ang = (l < 16) ? (float)exp2(-(10.0 / 15.0) * (double)l) : 0.0f;
    float th = (float)t * ang;
    float s, c;
    sincosf(th, &s, &c);
    float qa = (q0 * c + q1 * s) * ATTN_SCALE;
    float qb_ = (q1 * c - q0 * s) * ATTN_SCALE;
    float ka = k0 * c + k1 * s;
    float kb_ = k1 * c - k0 * s;

    size_t o = ((size_t)(b * HH + h) * TT + t) * DD + l;
    split_store(qh, ql, o,      qa);
    split_store(qh, ql, o + 32, qb_);
    split_store(kh, kl, o,      ka);
    split_store(kh, kl, o + 32, kb_);
    split_store(vh, vl, o,      v0);
    split_store(vh, vl, o + 32, v1);
}

// =================================================================
// V transpose: (B*H, T, D) -> (B*H, D, T), both hi and lo.
// =================================================================
__global__ __launch_bounds__(256)
void transpose_v(const __nv_bfloat16* __restrict__ vh,
                 const __nv_bfloat16* __restrict__ vl,
                 __nv_bfloat16* __restrict__ vth,
                 __nv_bfloat16* __restrict__ vtl)
{
    __shared__ uint16_t th[64][65], tl[64][65];
    const int bh = blockIdx.y, tb = blockIdx.x;
    const int r = threadIdx.x >> 2;
    const int cs = (threadIdx.x & 3) * 16;

    const size_t src = ((size_t)bh * TT + tb * 64 + r) * DD + cs;
    const uint32_t* ph = (const uint32_t*)(vh + src);
    const uint32_t* pl = (const uint32_t*)(vl + src);
#pragma unroll
    for (int j = 0; j < 8; j++) {
        uint32_t wh_ = ph[j], wl_ = pl[j];
        th[r][cs + 2 * j] = (uint16_t)(wh_ & 0xffff);
        th[r][cs + 2 * j + 1] = (uint16_t)(wh_ >> 16);
        tl[r][cs + 2 * j] = (uint16_t)(wl_ & 0xffff);
        tl[r][cs + 2 * j + 1] = (uint16_t)(wl_ >> 16);
    }
    __syncthreads();
    const size_t dst = ((size_t)bh * DD + r) * TT + tb * 64 + cs;
    uint32_t* oh = (uint32_t*)(vth + dst);
    uint32_t* ol = (uint32_t*)(vtl + dst);
#pragma unroll
    for (int j = 0; j < 8; j++) {
        oh[j] = (uint32_t)th[cs + 2 * j][r] | ((uint32_t)th[cs + 2 * j + 1][r] << 16);
        ol[j] = (uint32_t)tl[cs + 2 * j][r] | ((uint32_t)tl[cs + 2 * j + 1][r] << 16);
    }
}

// =================================================================
// Tensor-core flash attention (causal, no-max softmax, bf16x3).
// BQ=64, BKV=64, 256 threads, 2 CTAs/SM (112.6 KB smem).
// Warp tiles: S 16x32 (wm=(wid&3)*16, wnS=(wid>>2)*32),
//             PV 16 rows x 32 d (same wm, wnP=(wid>>2)*32).
// Smem words: QH 0, QL 2304, KV 4608 (2 bufs x 4 arr x 2304),
//             PH 23040, PL 25344, LP 27648 (+512).
// =================================================================
#define FL_SROW 36
#define FLQ_H 0
#define FLQ_L 2304
#define FLKV 4608
#define FLP_H 23040
#define FLP_L 25344
#define FLLP 27648
#define FL_SMEM ((27648 + 512) * 4)   // 112640 B

__global__ __launch_bounds__(256, 2)
void flash_mma(const __nv_bfloat16* __restrict__ qh, const __nv_bfloat16* __restrict__ ql,
               const __nv_bfloat16* __restrict__ kh, const __nv_bfloat16* __restrict__ kl,
               const __nv_bfloat16* __restrict__ vth, const __nv_bfloat16* __restrict__ vtl,
               __nv_bfloat16* __restrict__ yh, __nv_bfloat16* __restrict__ yl)
{
    extern __shared__ uint32_t sw[];
    const uint32_t sb = smem_u32(sw);
    const int tid = threadIdx.x;
    const int wid = tid >> 5;
    const int lane = tid & 31;
    const int g = lane >> 2;
    const int tig = lane & 3;
    const int bh = blockIdx.y;
    const int qb = (int)gridDim.x - 1 - (int)blockIdx.x;   // heavy first

    const int wm  = (wid & 3) * 16;     // rows (S and PV)
    const int wnS = (wid >> 2) * 32;    // key slice (S)
    const int wnP = (wid >> 2) * 32;    // d slice (PV)

    const uint32_t a16 = ((uint32_t)((lane & 15) * FL_SROW + (lane >> 4) * 4)) * 4;
    const uint32_t b8  = ((uint32_t)((lane & 7) * FL_SROW + ((lane >> 3) & 1) * 4)) * 4;

    const size_t base = (size_t)bh * TT * DD;

    // ---- Q tile load: 2 arrays x 64 rows x 2 halves ----
    {
        const int arr = tid >> 7;
        const int rowq = (tid >> 1) & 63;
        const int half = tid & 1;
        const __nv_bfloat16* src = (arr ? ql : qh) + base +
                                   ((size_t)(qb * 64 + rowq)) * 64 + half * 32;
        const uint32_t dst = sb + ((arr ? FLQ_L : FLQ_H) + rowq * FL_SROW + half * 16) * 4;
#pragma unroll
        for (int s = 0; s < 4; s++) CP_ASYNC(dst + s * 16, src + s * 8);
    }

    // KV loader mapping: 4 arrays x 64 rows
    const int kvarr = tid >> 6;          // 0:Kh 1:Kl 2:Vth 3:Vtl
    const int kvrow = tid & 63;
    const bool kvisV = kvarr >= 2;
    const __nv_bfloat16* kvbase =
        (kvarr == 0) ? (kh + base) : (kvarr == 1) ? (kl + base)
        : (kvarr == 2) ? (vth + base) : (vtl + base);
    const uint32_t kvdst0 = sb + (FLKV + kvarr * 2304 + kvrow * FL_SROW) * 4;

    auto issueKV = [&](int kb, int buf) {
        const __nv_bfloat16* src = kvisV
            ? (kvbase + (size_t)kvrow * TT + kb * 64)
            : (kvbase + ((size_t)(kb * 64 + kvrow)) * 64);
        const uint32_t dst = kvdst0 + buf * 9216 * 4;
#pragma unroll
        for (int s = 0; s < 8; s++) CP_ASYNC(dst + s * 16, src + s * 8);
    };

    const int nkb = qb + 1;
    issueKV(0, 0); CP_COMMIT();          // group: Q + KV0
    if (nkb > 1) issueKV(1, 1);
    CP_COMMIT();
    CP_WAIT1();
    __syncthreads();

    float O[4][4];
    float lp[2] = {0.0f, 0.0f};
#pragma unroll
    for (int nt = 0; nt < 4; nt++)
#pragma unroll
        for (int r = 0; r < 4; r++) O[nt][r] = 0.0f;

    for (int kb = 0; kb < nkb; kb++) {
        const int buf = kb & 1;
        const uint32_t Khb = sb + (FLKV + buf * 9216) * 4;
        const uint32_t Klb = Khb + 2304 * 4;
        const uint32_t Vhb = Khb + 4608 * 4;
        const uint32_t Vlb = Khb + 6912 * 4;

        // ---- S = Q K^T (bf16x3, ldmatrix) ----
        float S[4][4];
#pragma unroll
        for (int nt = 0; nt < 4; nt++)
#pragma unroll
            for (int r = 0; r < 4; r++) S[nt][r] = 0.0f;

#pragma unroll
        for (int ks = 0; ks < 4; ks++) {
            const uint32_t kwb = ks * 32;
            uint32_t bhf[4][2], blf[4][2];
#pragma unroll
            for (int nt = 0; nt < 4; nt++) {
                LDSM_X2(bhf[nt], Khb + b8 + (wnS + nt * 8) * (FL_SROW * 4) + kwb);
                LDSM_X2(blf[nt], Klb + b8 + (wnS + nt * 8) * (FL_SROW * 4) + kwb);
            }
            uint32_t ah[4], al[4];
            LDSM_X4(ah, sb + FLQ_H * 4 + a16 + wm * (FL_SROW * 4) + kwb);
            LDSM_X4(al, sb + FLQ_L * 4 + a16 + wm * (FL_SROW * 4) + kwb);
#pragma unroll
            for (int nt = 0; nt < 4; nt++) {
                mma16816(S[nt], ah, bhf[nt]);
                mma16816(S[nt], ah, blf[nt]);
                mma16816(S[nt], al, bhf[nt]);
            }
        }

        // ---- exp (no max), row-sum partials, write P hi/lo ----
        const bool diag = (kb == qb);
#pragma unroll
        for (int nt = 0; nt < 4; nt++) {
            const int c0 = kb * 64 + wnS + nt * 8 + tig * 2;
#pragma unroll
            for (int h2 = 0; h2 < 2; h2++) {
                const int r = wm + g + h2 * 8;
                const int grow = qb * 64 + r;
                float s0 = S[nt][h2 * 2 + 0];
                float s1 = S[nt][h2 * 2 + 1];
                float p0 = (diag && (c0 > grow)) ? 0.0f : __expf(s0);
                float p1 = (diag && (c0 + 1 > grow)) ? 0.0f : __expf(s1);
                lp[h2] += p0 + p1;
                __nv_bfloat16 hb0 = __float2bfloat16(p0);
                __nv_bfloat16 hb1 = __float2bfloat16(p1);
                const uint32_t hw = (uint32_t)__bfloat16_as_ushort(hb0) |
                                    ((uint32_t)__bfloat16_as_ushort(hb1) << 16);
                const uint32_t lw = pack_bf16(p0 - __bfloat162float(hb0),
                                              p1 - __bfloat162float(hb1));
                const uint32_t off = (uint32_t)(r * FL_SROW + (wnS >> 1) + nt * 4 + tig);
                sw[FLP_H + off] = hw;
                sw[FLP_L + off] = lw;
            }
        }
        __syncthreads();

        // ---- O += P V (bf16x3, ldmatrix) ----
#pragma unroll
        for (int ks = 0; ks < 4; ks++) {
            const uint32_t kwb = ks * 32;
            uint32_t bvh[4][2], bvl[4][2];
#pragma unroll
            for (int nt = 0; nt < 4; nt++) {
                LDSM_X2(bvh[nt], Vhb + b8 + (wnP + nt * 8) * (FL_SROW * 4) + kwb);
                LDSM_X2(bvl[nt], Vlb + b8 + (wnP + nt * 8) * (FL_SROW * 4) + kwb);
            }
            uint32_t aph[4], apl[4];
            LDSM_X4(aph, sb + FLP_H * 4 + a16 + wm * (FL_SROW * 4) + kwb);
            LDSM_X4(apl, sb + FLP_L * 4 + a16 + wm * (FL_SROW * 4) + kwb);
#pragma unroll
            for (int nt = 0; nt < 4; nt++) {
                mma16816(O[nt], aph, bvh[nt]);
                mma16816(O[nt], aph, bvl[nt]);
                mma16816(O[nt], apl, bvh[nt]);
            }
        }
        __syncthreads();
        if (kb + 2 < nkb) issueKV(kb + 2, buf);
        CP_COMMIT();
        CP_WAIT1();
        __syncthreads();
    }

    // ---- row-sum reduce: over tig lanes, then across the 2 key-slice warps ----
    float* lpf = (float*)(sw + FLLP);
#pragma unroll
    for (int i = 0; i < 2; i++) {
        lp[i] += __shfl_xor_sync(0xffffffffu, lp[i], 1);
        lp[i] += __shfl_xor_sync(0xffffffffu, lp[i], 2);
    }
    if (tig == 0) {
        lpf[(wid >> 2) * 64 + wm + g] = lp[0];
        lpf[(wid >> 2) * 64 + wm + g + 8] = lp[1];
    }
    __syncthreads();

    // ---- epilogue: O/l -> y bf16 hi/lo, (M, C) layout ----
    const int b = bh >> 4;
    const int h = bh & 15;
#pragma unroll
    for (int h2 = 0; h2 < 2; h2++) {
        const int r = wm + g + h2 * 8;
        const float lsum = lpf[r] + lpf[64 + r];
        const float linv = 1.0f / lsum;
        const int t = qb * 64 + r;
        const size_t rowoff = ((size_t)(b * TT + t)) * CC + h * 64 + wnP;
#pragma unroll
        for (int nt = 0; nt < 4; nt++) {
            float o0 = O[nt][h2 * 2 + 0] * linv;
            float o1 = O[nt][h2 * 2 + 1] * linv;
            __nv_bfloat16 hb0 = __float2bfloat16(o0);
            __nv_bfloat16 hb1 = __float2bfloat16(o1);
            const size_t col = rowoff + nt * 8 + tig * 2;
            *(uint32_t*)(yh + col) = (uint32_t)__bfloat16_as_ushort(hb0) |
                                     ((uint32_t)__bfloat16_as_ushort(hb1) << 16);
            *(uint32_t*)(yl + col) = pack_bf16(o0 - __bfloat162float(hb0),
                                               o1 - __bfloat162float(hb1));
        }
    }
}

// =================================================================
// launch
// =================================================================
extern "C" void kernel_launch(void* const* d_in, const int* in_sizes, int n_in,
                              void* d_out, int out_size)
{
    const float* x        = (const float*)d_in[0];
    const float* ve       = (const float*)d_in[1];
    const float* qkv_w    = (const float*)d_in[2];
    const float* lambdas  = (const float*)d_in[3];
    const float* c_proj_w = (const float*)d_in[4];
    float* out = (float*)d_out;

    float* qkv_p;
    cudaGetSymbolAddress((void**)&qkv_p, g_qkv);
    __nv_bfloat16 *xh, *xl, *wh, *wl, *yh, *yl, *ph, *pl;
    cudaGetSymbolAddress((void**)&xh, g_xh); cudaGetSymbolAddress((void**)&xl, g_xl);
    cudaGetSymbolAddress((void**)&wh, g_wh); cudaGetSymbolAddress((void**)&wl, g_wl);
    cudaGetSymbolAddress((void**)&yh, g_yh); cudaGetSymbolAddress((void**)&yl, g_yl);
    cudaGetSymbolAddress((void**)&ph, g_ph); cudaGetSymbolAddress((void**)&pl, g_pl);
    __nv_bfloat16 *qh, *ql, *kh, *kl, *vh, *vl, *vth, *vtl;
    cudaGetSymbolAddress((void**)&qh, g_qh); cudaGetSymbolAddress((void**)&ql, g_ql);
    cudaGetSymbolAddress((void**)&kh, g_kh); cudaGetSymbolAddress((void**)&kl, g_kl);
    cudaGetSymbolAddress((void**)&vh, g_vh); cudaGetSymbolAddress((void**)&vl, g_vl);
    cudaGetSymbolAddress((void**)&vth, g_vth); cudaGetSymbolAddress((void**)&vtl, g_vtl);

    cudaFuncSetAttribute(mma_gemm_pre, cudaFuncAttributeMaxDynamicSharedMemorySize, GEMM_SMEM);
    cudaFuncSetAttribute(flash_mma, cudaFuncAttributeMaxDynamicSharedMemorySize, FL_SMEM);

    // 0) pre-split fp32 -> bf16 hi/lo
    split_bf16<<<(MM * CC) / 1024, 256>>>(x, xh, xl, MM * CC);
    split_bf16<<<(N_QKV * CC) / 1024, 256>>>(qkv_w, wh, wl, N_QKV * CC);

    // 1) qkv = x @ qkv_w^T
    mma_gemm_pre<<<dim3(N_QKV / 128, MM / 128), 256, GEMM_SMEM>>>(
        xh, xl, wh, wl, qkv_p, MM, N_QKV, CC);

    // 2) v-mix + rmsnorm + rotary -> bf16 hi/lo (q scaled by ATTN_SCALE)
    postproc<<<(MM * HH) / 8, 256>>>(qkv_p, ve, lambdas, qh, ql, kh, kl, vh, vl);

    // 2b) transpose V to (B*H, D, T)
    transpose_v<<<dim3(TT / 64, BB * HH), 256>>>(vh, vl, vth, vtl);

    // 3) tensor-core causal flash attention -> y bf16 hi/lo
    flash_mma<<<dim3(TT / 64, BB * HH), 256, FL_SMEM>>>(
        qh, ql, kh, kl, vth, vtl, yh, yl);

    // 4) out = y @ c_proj_w^T
    split_bf16<<<(CC * CC) / 1024, 256>>>(c_proj_w, ph, pl, CC * CC);
    mma_gemm_pre<<<dim3(CC / 128, MM / 128), 256, GEMM_SMEM>>>(
        yh, yl, ph, pl, out, MM, CC, CC);
}

// round 11
// speedup vs baseline: 1.0722x; 1.0722x over previous
#include <cuda_runtime.h>
#include <cuda_bf16.h>
#include <math.h>
#include <stdint.h>

// Problem constants
#define BB 4
#define TT 2048
#define CC 1024
#define HH 16
#define DD 64
#define MM (BB * TT)         // 8192
#define N_QKV (3 * CC)       // 3072
#define ATTN_SCALE 0.12f
#define RMS_EPS 1e-6f

// ---------------- device scratch (allocation-free) ----------------
__device__ float g_qkv[(size_t)MM * N_QKV];          // (M, 3C)
__device__ __nv_bfloat16 g_xh[(size_t)MM * CC],     g_xl[(size_t)MM * CC];
__device__ __nv_bfloat16 g_wh[(size_t)N_QKV * CC],  g_wl[(size_t)N_QKV * CC];
__device__ __nv_bfloat16 g_yh[(size_t)MM * CC],     g_yl[(size_t)MM * CC];
__device__ __nv_bfloat16 g_ph[(size_t)CC * CC],     g_pl[(size_t)CC * CC];
#define AHD ((size_t)BB * HH * TT * DD)
__device__ __nv_bfloat16 g_qh[AHD], g_ql[AHD];
__device__ __nv_bfloat16 g_kh[AHD], g_kl[AHD];
__device__ __nv_bfloat16 g_vh[AHD], g_vl[AHD];
__device__ __nv_bfloat16 g_vth[AHD], g_vtl[AHD];

// =================================================================
// common helpers
// =================================================================
__device__ __forceinline__ uint32_t smem_u32(const void* p) {
    uint32_t a;
    asm("{ .reg .u64 t; cvta.to.shared.u64 t, %1; cvt.u32.u64 %0, t; }"
        : "=r"(a) : "l"(p));
    return a;
}

__device__ __forceinline__ void mma16816(float* d, const uint32_t* a, const uint32_t* b) {
    asm volatile(
        "mma.sync.aligned.m16n8k16.row.col.f32.bf16.bf16.f32 "
        "{%0,%1,%2,%3}, {%4,%5,%6,%7}, {%8,%9}, {%0,%1,%2,%3};"
        : "+f"(d[0]), "+f"(d[1]), "+f"(d[2]), "+f"(d[3])
        : "r"(a[0]), "r"(a[1]), "r"(a[2]), "r"(a[3]), "r"(b[0]), "r"(b[1]));
}

#define LDSM_X4(r, addr) \
    asm volatile("ldmatrix.sync.aligned.m8n8.x4.shared.b16 {%0,%1,%2,%3}, [%4];" \
                 : "=r"((r)[0]), "=r"((r)[1]), "=r"((r)[2]), "=r"((r)[3]) : "r"(addr))
#define LDSM_X2(r, addr) \
    asm volatile("ldmatrix.sync.aligned.m8n8.x2.shared.b16 {%0,%1}, [%2];" \
                 : "=r"((r)[0]), "=r"((r)[1]) : "r"(addr))

#define CP_ASYNC(dst, src) \
    asm volatile("cp.async.cg.shared.global [%0], [%1], 16;" \
                 :: "r"(dst), "l"(src) : "memory")
#define CP_COMMIT() asm volatile("cp.async.commit_group;" ::: "memory")
#define CP_WAIT1()  asm volatile("cp.async.wait_group 1;" ::: "memory")

__device__ __forceinline__ uint32_t pack_bf16(float a, float b) {
    __nv_bfloat16 ha = __float2bfloat16(a);
    __nv_bfloat16 hb = __float2bfloat16(b);
    return (uint32_t)__bfloat16_as_ushort(ha) |
           ((uint32_t)__bfloat16_as_ushort(hb) << 16);
}

// =================================================================
// split: fp32 -> bf16 hi + bf16 lo (residual)
// =================================================================
__global__ __launch_bounds__(256)
void split_bf16(const float* __restrict__ in,
                __nv_bfloat16* __restrict__ hi, __nv_bfloat16* __restrict__ lo,
                int n)
{
    const int i = (blockIdx.x * 256 + threadIdx.x) * 4;
    if (i >= n) return;
    float4 f4 = *(const float4*)(in + i);
    float f[4] = {f4.x, f4.y, f4.z, f4.w};
    uint16_t h[4], l[4];
#pragma unroll
    for (int j = 0; j < 4; j++) {
        __nv_bfloat16 hb = __float2bfloat16(f[j]);
        __nv_bfloat16 lb = __float2bfloat16(f[j] - __bfloat162float(hb));
        h[j] = __bfloat16_as_ushort(hb);
        l[j] = __bfloat16_as_ushort(lb);
    }
    *(uint2*)(hi + i) = make_uint2((uint32_t)h[0] | ((uint32_t)h[1] << 16),
                                   (uint32_t)h[2] | ((uint32_t)h[3] << 16));
    *(uint2*)(lo + i) = make_uint2((uint32_t)l[0] | ((uint32_t)l[1] << 16),
                                   (uint32_t)l[2] | ((uint32_t)l[3] << 16));
}

// =================================================================
// mma.sync bf16x3 GEMM (pre-split, cp.async double buffer, ldmatrix;
// B fragments fetched with x4 ldmatrix: both k-halves of 2 n-tiles).
// =================================================================
#define SROW 20
#define ARR_W (128 * SROW)
#define BUF_W (4 * ARR_W)
#define GEMM_SMEM (2 * BUF_W * 4)

__global__ __launch_bounds__(256, 2)
void mma_gemm_pre(const __nv_bfloat16* __restrict__ Ahg,
                  const __nv_bfloat16* __restrict__ Alg,
                  const __nv_bfloat16* __restrict__ Bhg,
                  const __nv_bfloat16* __restrict__ Blg,
                  float* __restrict__ C, int M, int N, int K)
{
    extern __shared__ uint32_t sw[];
    const uint32_t sbase = smem_u32(sw);

    const int tid = threadIdx.x;
    const int wid = tid >> 5;
    const int lane = tid & 31;
    const int g = lane >> 2;
    const int tig = lane & 3;
    const int wm = (wid & 1) * 64;
    const int wn = (wid >> 1) * 32;

    const int bm = blockIdx.y * 128;
    const int bn = blockIdx.x * 128;

    const int s0 = tid * 2;
    const int lrow0 = s0 >> 2, lseg0 = s0 & 3;
    const int lrow1 = (s0 + 1) >> 2, lseg1 = (s0 + 1) & 3;

    // A x4 offset: 16 rows, k-half by lane>>4
    const uint32_t a16 = ((uint32_t)((wm + (lane & 15)) * SROW + (lane >> 4) * 4)) * 4;
    // B x4 offset: 4 matrices = (nt0,k0),(nt0,k1),(nt1,k0),(nt1,k1)
    //   rows: lanes 0-15 -> nt0 rows (lane&7), lanes 16-31 -> nt1 rows (+8)
    //   k-half: (lane>>3)&1
    const uint32_t b8q = ((uint32_t)((wn + ((lane >> 4) << 3) + (lane & 7)) * SROW +
                                     ((lane >> 3) & 1) * 4)) * 4;

    float acc[4][4][4];
#pragma unroll
    for (int mt = 0; mt < 4; mt++)
#pragma unroll
        for (int nt = 0; nt < 4; nt++)
#pragma unroll
            for (int r = 0; r < 4; r++) acc[mt][nt][r] = 0.0f;

    const int nch = K >> 5;

    auto issue = [&](int ci, int buf) {
        const int kc = ci << 5;
        const uint32_t bb = sbase + buf * (BUF_W * 4);
#pragma unroll
        for (int j = 0; j < 2; j++) {
            const int row = j ? lrow1 : lrow0;
            const int seg = j ? lseg1 : lseg0;
            const size_t goff = (size_t)(bm + row) * K + kc + seg * 8;
            const size_t goffB = (size_t)(bn + row) * K + kc + seg * 8;
            const uint32_t soff = (row * SROW + seg * 4) * 4;
            CP_ASYNC(bb + 0 * ARR_W * 4 + soff, Ahg + goff);
            CP_ASYNC(bb + 1 * ARR_W * 4 + soff, Alg + goff);
            CP_ASYNC(bb + 2 * ARR_W * 4 + soff, Bhg + goffB);
            CP_ASYNC(bb + 3 * ARR_W * 4 + soff, Blg + goffB);
        }
    };

    issue(0, 0); CP_COMMIT();
    issue(1, 1); CP_COMMIT();

    for (int ci = 0; ci < nch; ci++) {
        const int buf = ci & 1;
        CP_WAIT1();
        __syncthreads();

        const uint32_t Ah_b = sbase + buf * (BUF_W * 4);
        const uint32_t Al_b = Ah_b + ARR_W * 4;
        const uint32_t Bh_b = Ah_b + 2 * ARR_W * 4;
        const uint32_t Bl_b = Ah_b + 3 * ARR_W * 4;

#pragma unroll
        for (int ks = 0; ks < 2; ks++) {
            const uint32_t kwb = ks * 32;
            uint32_t bhf[4][2], blf[4][2];
#pragma unroll
            for (int ntp = 0; ntp < 2; ntp++) {
                uint32_t q[4];
                LDSM_X4(q, Bh_b + b8q + ntp * (16 * SROW * 4) + kwb);
                bhf[2 * ntp][0] = q[0]; bhf[2 * ntp][1] = q[1];
                bhf[2 * ntp + 1][0] = q[2]; bhf[2 * ntp + 1][1] = q[3];
                LDSM_X4(q, Bl_b + b8q + ntp * (16 * SROW * 4) + kwb);
                blf[2 * ntp][0] = q[0]; blf[2 * ntp][1] = q[1];
                blf[2 * ntp + 1][0] = q[2]; blf[2 * ntp + 1][1] = q[3];
            }
#pragma unroll
            for (int mt = 0; mt < 4; mt++) {
                uint32_t ah[4], al[4];
                LDSM_X4(ah, Ah_b + a16 + mt * (16 * SROW * 4) + kwb);
                LDSM_X4(al, Al_b + a16 + mt * (16 * SROW * 4) + kwb);
#pragma unroll
                for (int nt = 0; nt < 4; nt++) {
                    mma16816(acc[mt][nt], ah, bhf[nt]);
                    mma16816(acc[mt][nt], ah, blf[nt]);
                    mma16816(acc[mt][nt], al, bhf[nt]);
                }
            }
        }
        __syncthreads();
        if (ci + 2 < nch) issue(ci + 2, buf);
        CP_COMMIT();
    }

#pragma unroll
    for (int mt = 0; mt < 4; mt++) {
        const int r0 = bm + wm + mt * 16 + g;
#pragma unroll
        for (int nt = 0; nt < 4; nt++) {
            const int col = bn + wn + nt * 8 + tig * 2;
            *(float2*)&C[(size_t)r0 * N + col] =
                make_float2(acc[mt][nt][0], acc[mt][nt][1]);
            *(float2*)&C[(size_t)(r0 + 8) * N + col] =
                make_float2(acc[mt][nt][2], acc[mt][nt][3]);
        }
    }
}

// =================================================================
// Post-process: v-mix, rmsnorm, rotary; q pre-scaled by ATTN_SCALE;
// outputs bf16 hi/lo q,k,v in (B*H, T, D) layout.
// =================================================================
__device__ __forceinline__ void split_store(__nv_bfloat16* H, __nv_bfloat16* L,
                                            size_t o, float f) {
    __nv_bfloat16 hb = __float2bfloat16(f);
    H[o] = hb;
    L[o] = __float2bfloat16(f - __bfloat162float(hb));
}

__global__ __launch_bounds__(256)
void postproc(const float* __restrict__ qkv, const float* __restrict__ ve,
              const float* __restrict__ lambdas,
              __nv_bfloat16* __restrict__ qh, __nv_bfloat16* __restrict__ ql,
              __nv_bfloat16* __restrict__ kh, __nv_bfloat16* __restrict__ kl,
              __nv_bfloat16* __restrict__ vh, __nv_bfloat16* __restrict__ vl)
{
    const int pair = blockIdx.x * 8 + (threadIdx.x >> 5);
    const int l = threadIdx.x & 31;
    const int m = pair >> 4;
    const int h = pair & 15;
    const int t = m & (TT - 1);
    const int b = m >> 11;

    const float* row = qkv + (size_t)m * N_QKV + h * DD;
    float q0 = row[l],          q1 = row[l + 32];
    float k0 = row[CC + l],     k1 = row[CC + l + 32];
    float v0 = row[2 * CC + l], v1 = row[2 * CC + l + 32];

    const float lam0 = lambdas[0], lam1 = lambdas[1];
    const float* verow = ve + (size_t)m * CC + h * DD;
    v0 = lam0 * v0 + lam1 * verow[l];
    v1 = lam0 * v1 + lam1 * verow[l + 32];

    float sq = q0 * q0 + q1 * q1;
    float sk = k0 * k0 + k1 * k1;
#pragma unroll
    for (int o = 16; o; o >>= 1) {
        sq += __shfl_xor_sync(0xffffffffu, sq, o);
        sk += __shfl_xor_sync(0xffffffffu, sk, o);
    }
    float rq = 1.0f / sqrtf(sq * (1.0f / 64.0f) + RMS_EPS);
    float rk = 1.0f / sqrtf(sk * (1.0f / 64.0f) + RMS_EPS);
    q0 *= rq; q1 *= rq;
    k0 *= rk; k1 *= rk;

    float ang = (l < 16) ? (float)exp2(-(10.0 / 15.0) * (double)l) : 0.0f;
    float th = (float)t * ang;
    float s, c;
    sincosf(th, &s, &c);
    float qa = (q0 * c + q1 * s) * ATTN_SCALE;
    float qb_ = (q1 * c - q0 * s) * ATTN_SCALE;
    float ka = k0 * c + k1 * s;
    float kb_ = k1 * c - k0 * s;

    size_t o = ((size_t)(b * HH + h) * TT + t) * DD + l;
    split_store(qh, ql, o,      qa);
    split_store(qh, ql, o + 32, qb_);
    split_store(kh, kl, o,      ka);
    split_store(kh, kl, o + 32, kb_);
    split_store(vh, vl, o,      v0);
    split_store(vh, vl, o + 32, v1);
}

// =================================================================
// V transpose: (B*H, T, D) -> (B*H, D, T), both hi and lo.
// =================================================================
__global__ __launch_bounds__(256)
void transpose_v(const __nv_bfloat16* __restrict__ vh,
                 const __nv_bfloat16* __restrict__ vl,
                 __nv_bfloat16* __restrict__ vth,
                 __nv_bfloat16* __restrict__ vtl)
{
    __shared__ uint16_t th[64][65], tl[64][65];
    const int bh = blockIdx.y, tb = blockIdx.x;
    const int r = threadIdx.x >> 2;
    const int cs = (threadIdx.x & 3) * 16;

    const size_t src = ((size_t)bh * TT + tb * 64 + r) * DD + cs;
    const uint32_t* ph = (const uint32_t*)(vh + src);
    const uint32_t* pl = (const uint32_t*)(vl + src);
#pragma unroll
    for (int j = 0; j < 8; j++) {
        uint32_t wh_ = ph[j], wl_ = pl[j];
        th[r][cs + 2 * j] = (uint16_t)(wh_ & 0xffff);
        th[r][cs + 2 * j + 1] = (uint16_t)(wh_ >> 16);
        tl[r][cs + 2 * j] = (uint16_t)(wl_ & 0xffff);
        tl[r][cs + 2 * j + 1] = (uint16_t)(wl_ >> 16);
    }
    __syncthreads();
    const size_t dst = ((size_t)bh * DD + r) * TT + tb * 64 + cs;
    uint32_t* oh = (uint32_t*)(vth + dst);
    uint32_t* ol = (uint32_t*)(vtl + dst);
#pragma unroll
    for (int j = 0; j < 8; j++) {
        oh[j] = (uint32_t)th[cs + 2 * j][r] | ((uint32_t)th[cs + 2 * j + 1][r] << 16);
        ol[j] = (uint32_t)tl[cs + 2 * j][r] | ((uint32_t)tl[cs + 2 * j + 1][r] << 16);
    }
}

// =================================================================
// Tensor-core flash attention (causal, no-max softmax, bf16x3),
// fragments via ldmatrix. BQ=128, BKV=64 (R9 configuration).
// =================================================================
#define FL_SROW 36
#define FL_QH 0
#define FL_QL 4608
#define FL_KV 9216
#define FL_PH 27648
#define FL_PL 32256
#define FL_LP 36864
#define FL_SMEM ((36864 + 512) * 4)

__global__ __launch_bounds__(256, 1)
void flash_mma(const __nv_bfloat16* __restrict__ qh, const __nv_bfloat16* __restrict__ ql,
               const __nv_bfloat16* __restrict__ kh, const __nv_bfloat16* __restrict__ kl,
               const __nv_bfloat16* __restrict__ vth, const __nv_bfloat16* __restrict__ vtl,
               __nv_bfloat16* __restrict__ yh, __nv_bfloat16* __restrict__ yl)
{
    extern __shared__ uint32_t sw[];
    const uint32_t sb = smem_u32(sw);
    const int tid = threadIdx.x;
    const int wid = tid >> 5;
    const int lane = tid & 31;
    const int g = lane >> 2;
    const int tig = lane & 3;
    const int bh = blockIdx.y;
    const int qb = (int)gridDim.x - 1 - (int)blockIdx.x;   // heavy first

    const int wmS = (wid & 1) * 64, wnS = (wid >> 1) * 16;
    const int wmP = (wid & 3) * 32, wnP = (wid >> 2) * 32;

    const uint32_t a16 = ((uint32_t)(((lane & 15)) * FL_SROW + (lane >> 4) * 4)) * 4;
    const uint32_t b8  = ((uint32_t)(((lane & 7)) * FL_SROW + ((lane >> 3) & 1) * 4)) * 4;

    const size_t base = (size_t)bh * TT * DD;

    // ---- Q tile load (cp.async) ----
    {
        const int arr = tid >> 7;
        const int row = tid & 127;
        const __nv_bfloat16* src = (arr ? ql : qh) + base + ((size_t)(qb * 128 + row)) * 64;
        const uint32_t dst = sb + ((arr ? FL_QL : FL_QH) + row * FL_SROW) * 4;
#pragma unroll
        for (int s = 0; s < 8; s++) CP_ASYNC(dst + s * 16, src + s * 8);
    }

    const int kvarr = tid >> 6;
    const int kvrow = tid & 63;
    const bool kvisV = kvarr >= 2;
    const __nv_bfloat16* kvbase =
        (kvarr == 0) ? (kh + base) : (kvarr == 1) ? (kl + base)
        : (kvarr == 2) ? (vth + base) : (vtl + base);
    const uint32_t kvdst0 = sb + (FL_KV + (kvarr & 3) * 2304 + kvrow * FL_SROW) * 4;

    auto issueKV = [&](int kb, int buf) {
        const __nv_bfloat16* src = kvisV
            ? (kvbase + (size_t)kvrow * TT + kb * 64)
            : (kvbase + ((size_t)(kb * 64 + kvrow)) * 64);
        const uint32_t dst = kvdst0 + buf * 9216 * 4;
#pragma unroll
        for (int s = 0; s < 8; s++) CP_ASYNC(dst + s * 16, src + s * 8);
    };

    const int nkb = 2 * qb + 2;
    issueKV(0, 0); CP_COMMIT();
    if (nkb > 1) issueKV(1, 1);
    CP_COMMIT();
    CP_WAIT1();
    __syncthreads();

    float O[2][4][4];
    float lp[8];
#pragma unroll
    for (int i = 0; i < 8; i++) lp[i] = 0.0f;
#pragma unroll
    for (int mt = 0; mt < 2; mt++)
#pragma unroll
        for (int nt = 0; nt < 4; nt++)
#pragma unroll
            for (int r = 0; r < 4; r++) O[mt][nt][r] = 0.0f;

    for (int kb = 0; kb < nkb; kb++) {
        const int buf = kb & 1;
        const uint32_t Khb = sb + (FL_KV + buf * 9216) * 4;
        const uint32_t Klb = Khb + 2304 * 4;
        const uint32_t Vhb = Khb + 4608 * 4;
        const uint32_t Vlb = Khb + 6912 * 4;

        // ---- S = Q K^T (bf16x3, ldmatrix) ----
        float S[4][2][4];
#pragma unroll
        for (int mt = 0; mt < 4; mt++)
#pragma unroll
            for (int nt = 0; nt < 2; nt++)
#pragma unroll
                for (int r = 0; r < 4; r++) S[mt][nt][r] = 0.0f;

#pragma unroll
        for (int ks = 0; ks < 4; ks++) {
            const uint32_t kwb = ks * 32;
            uint32_t bhf[2][2], blf[2][2];
#pragma unroll
            for (int nt = 0; nt < 2; nt++) {
                LDSM_X2(bhf[nt], Khb + b8 + (wnS + nt * 8) * (FL_SROW * 4) + kwb);
                LDSM_X2(blf[nt], Klb + b8 + (wnS + nt * 8) * (FL_SROW * 4) + kwb);
            }
#pragma unroll
            for (int mt = 0; mt < 4; mt++) {
                uint32_t ah[4], al[4];
                LDSM_X4(ah, sb + FL_QH * 4 + a16 + (wmS + mt * 16) * (FL_SROW * 4) + kwb);
                LDSM_X4(al, sb + FL_QL * 4 + a16 + (wmS + mt * 16) * (FL_SROW * 4) + kwb);
#pragma unroll
                for (int nt = 0; nt < 2; nt++) {
                    mma16816(S[mt][nt], ah, bhf[nt]);
                    mma16816(S[mt][nt], ah, blf[nt]);
                    mma16816(S[mt][nt], al, bhf[nt]);
                }
            }
        }

        // ---- exp (no max), row-sum partials, write P hi/lo ----
        const bool diag = (kb >= 2 * qb);
#pragma unroll
        for (int mt = 0; mt < 4; mt++) {
            const int r0 = wmS + mt * 16 + g;
#pragma unroll
            for (int nt = 0; nt < 2; nt++) {
                const int c0 = kb * 64 + wnS + nt * 8 + tig * 2;
#pragma unroll
                for (int h2 = 0; h2 < 2; h2++) {
                    const int r = r0 + h2 * 8;
                    const int grow = qb * 128 + r;
                    float s0 = S[mt][nt][h2 * 2 + 0];
                    float s1 = S[mt][nt][h2 * 2 + 1];
                    float p0 = (diag && (c0 > grow)) ? 0.0f : __expf(s0);
                    float p1 = (diag && (c0 + 1 > grow)) ? 0.0f : __expf(s1);
                    lp[mt * 2 + h2] += p0 + p1;
                    __nv_bfloat16 hb0 = __float2bfloat16(p0);
                    __nv_bfloat16 hb1 = __float2bfloat16(p1);
                    const uint32_t hw = (uint32_t)__bfloat16_as_ushort(hb0) |
                                        ((uint32_t)__bfloat16_as_ushort(hb1) << 16);
                    const uint32_t lw = pack_bf16(p0 - __bfloat162float(hb0),
                                                  p1 - __bfloat162float(hb1));
                    const uint32_t off = (uint32_t)(r * FL_SROW + (wnS >> 1) + nt * 4 + tig);
                    sw[FL_PH + off] = hw;
                    sw[FL_PL + off] = lw;
                }
            }
        }
        __syncthreads();

        // ---- O += P V (bf16x3, ldmatrix) ----
#pragma unroll
        for (int ks = 0; ks < 4; ks++) {
            const uint32_t kwb = ks * 32;
            uint32_t bvh[4][2], bvl[4][2];
#pragma unroll
            for (int nt = 0; nt < 4; nt++) {
                LDSM_X2(bvh[nt], Vhb + b8 + (wnP + nt * 8) * (FL_SROW * 4) + kwb);
                LDSM_X2(bvl[nt], Vlb + b8 + (wnP + nt * 8) * (FL_SROW * 4) + kwb);
            }
#pragma unroll
            for (int mt = 0; mt < 2; mt++) {
                uint32_t aph[4], apl[4];
                LDSM_X4(aph, sb + FL_PH * 4 + a16 + (wmP + mt * 16) * (FL_SROW * 4) + kwb);
                LDSM_X4(apl, sb + FL_PL * 4 + a16 + (wmP + mt * 16) * (FL_SROW * 4) + kwb);
#pragma unroll
                for (int nt = 0; nt < 4; nt++) {
                    mma16816(O[mt][nt], aph, bvh[nt]);
                    mma16816(O[mt][nt], aph, bvl[nt]);
                    mma16816(O[mt][nt], apl, bvh[nt]);
                }
            }
        }
        __syncthreads();
        if (kb + 2 < nkb) issueKV(kb + 2, buf);
        CP_COMMIT();
        CP_WAIT1();
        __syncthreads();
    }

    // ---- row-sum reduce ----
    float* lpf = (float*)(sw + FL_LP);
#pragma unroll
    for (int i = 0; i < 8; i++) {
        lp[i] += __shfl_xor_sync(0xffffffffu, lp[i], 1);
        lp[i] += __shfl_xor_sync(0xffffffffu, lp[i], 2);
    }
    if (tig == 0) {
#pragma unroll
        for (int mt = 0; mt < 4; mt++) {
            lpf[wid * 64 + mt * 16 + g] = lp[mt * 2];
            lpf[wid * 64 + mt * 16 + g + 8] = lp[mt * 2 + 1];
        }
    }
    __syncthreads();

    // ---- epilogue ----
    const int b = bh >> 4;
    const int h = bh & 15;
#pragma unroll
    for (int mt = 0; mt < 2; mt++) {
#pragma unroll
        for (int h2 = 0; h2 < 2; h2++) {
            const int r = wmP + mt * 16 + g + h2 * 8;
            const int hm = r >> 6, r6 = r & 63;
            const float lsum = lpf[(hm + 0) * 64 + r6] + lpf[(hm + 2) * 64 + r6] +
                               lpf[(hm + 4) * 64 + r6] + lpf[(hm + 6) * 64 + r6];
            const float linv = 1.0f / lsum;
            const int t = qb * 128 + r;
            const size_t rowoff = ((size_t)(b * TT + t)) * CC + h * 64 + wnP;
#pragma unroll
            for (int nt = 0; nt < 4; nt++) {
                float o0 = O[mt][nt][h2 * 2 + 0] * linv;
                float o1 = O[mt][nt][h2 * 2 + 1] * linv;
                __nv_bfloat16 hb0 = __float2bfloat16(o0);
                __nv_bfloat16 hb1 = __float2bfloat16(o1);
                const size_t col = rowoff + nt * 8 + tig * 2;
                *(uint32_t*)(yh + col) = (uint32_t)__bfloat16_as_ushort(hb0) |
                                         ((uint32_t)__bfloat16_as_ushort(hb1) << 16);
                *(uint32_t*)(yl + col) = pack_bf16(o0 - __bfloat162float(hb0),
                                                   o1 - __bfloat162float(hb1));
            }
        }
    }
}

// =================================================================
// launch
// =================================================================
extern "C" void kernel_launch(void* const* d_in, const int* in_sizes, int n_in,
                              void* d_out, int out_size)
{
    const float* x        = (const float*)d_in[0];
    const float* ve       = (const float*)d_in[1];
    const float* qkv_w    = (const float*)d_in[2];
    const float* lambdas  = (const float*)d_in[3];
    const float* c_proj_w = (const float*)d_in[4];
    float* out = (float*)d_out;

    float* qkv_p;
    cudaGetSymbolAddress((void**)&qkv_p, g_qkv);
    __nv_bfloat16 *xh, *xl, *wh, *wl, *yh, *yl, *ph, *pl;
    cudaGetSymbolAddress((void**)&xh, g_xh); cudaGetSymbolAddress((void**)&xl, g_xl);
    cudaGetSymbolAddress((void**)&wh, g_wh); cudaGetSymbolAddress((void**)&wl, g_wl);
    cudaGetSymbolAddress((void**)&yh, g_yh); cudaGetSymbolAddress((void**)&yl, g_yl);
    cudaGetSymbolAddress((void**)&ph, g_ph); cudaGetSymbolAddress((void**)&pl, g_pl);
    __nv_bfloat16 *qh, *ql, *kh, *kl, *vh, *vl, *vth, *vtl;
    cudaGetSymbolAddress((void**)&qh, g_qh); cudaGetSymbolAddress((void**)&ql, g_ql);
    cudaGetSymbolAddress((void**)&kh, g_kh); cudaGetSymbolAddress((void**)&kl, g_kl);
    cudaGetSymbolAddress((void**)&vh, g_vh); cudaGetSymbolAddress((void**)&vl, g_vl);
    cudaGetSymbolAddress((void**)&vth, g_vth); cudaGetSymbolAddress((void**)&vtl, g_vtl);

    cudaFuncSetAttribute(mma_gemm_pre, cudaFuncAttributeMaxDynamicSharedMemorySize, GEMM_SMEM);
    cudaFuncSetAttribute(flash_mma, cudaFuncAttributeMaxDynamicSharedMemorySize, FL_SMEM);

    // 0) pre-split fp32 -> bf16 hi/lo
    split_bf16<<<(MM * CC) / 1024, 256>>>(x, xh, xl, MM * CC);
    split_bf16<<<(N_QKV * CC) / 1024, 256>>>(qkv_w, wh, wl, N_QKV * CC);

    // 1) qkv = x @ qkv_w^T
    mma_gemm_pre<<<dim3(N_QKV / 128, MM / 128), 256, GEMM_SMEM>>>(
        xh, xl, wh, wl, qkv_p, MM, N_QKV, CC);

    // 2) v-mix + rmsnorm + rotary -> bf16 hi/lo (q scaled by ATTN_SCALE)
    postproc<<<(MM * HH) / 8, 256>>>(qkv_p, ve, lambdas, qh, ql, kh, kl, vh, vl);

    // 2b) transpose V to (B*H, D, T)
    transpose_v<<<dim3(TT / 64, BB * HH), 256>>>(vh, vl, vth, vtl);

    // 3) tensor-core causal flash attention -> y bf16 hi/lo
    flash_mma<<<dim3(TT / 128, BB * HH), 256, FL_SMEM>>>(
        qh, ql, kh, kl, vth, vtl, yh, yl);

    // 4) out = y @ c_proj_w^T
    split_bf16<<<(CC * CC) / 1024, 256>>>(c_proj_w, ph, pl, CC * CC);
    mma_gemm_pre<<<dim3(CC / 128, MM / 128), 256, GEMM_SMEM>>>(
        yh, yl, ph, pl, out, MM, CC, CC);
}

// round 12
// speedup vs baseline: 1.1010x; 1.0269x over previous
#include <cuda_runtime.h>
#include <cuda_bf16.h>
#include <math.h>
#include <stdint.h>

// Problem constants
#define BB 4
#define TT 2048
#define CC 1024
#define HH 16
#define DD 64
#define MM (BB * TT)         // 8192
#define N_QKV (3 * CC)       // 3072
#define ATTN_SCALE 0.12f
#define RMS_EPS 1e-6f

// ---------------- device scratch (allocation-free) ----------------
__device__ float g_qkv[(size_t)MM * N_QKV];          // (M, 3C)
__device__ __nv_bfloat16 g_xh[(size_t)MM * CC],     g_xl[(size_t)MM * CC];
__device__ __nv_bfloat16 g_wh[(size_t)N_QKV * CC],  g_wl[(size_t)N_QKV * CC];
__device__ __nv_bfloat16 g_yh[(size_t)MM * CC],     g_yl[(size_t)MM * CC];
__device__ __nv_bfloat16 g_ph[(size_t)CC * CC],     g_pl[(size_t)CC * CC];
#define AHD ((size_t)BB * HH * TT * DD)
__device__ __nv_bfloat16 g_qh[AHD], g_ql[AHD];
__device__ __nv_bfloat16 g_kh[AHD], g_kl[AHD];
__device__ __nv_bfloat16 g_vh[AHD], g_vl[AHD];
__device__ __nv_bfloat16 g_vth[AHD], g_vtl[AHD];

// =================================================================
// common helpers
// =================================================================
__device__ __forceinline__ uint32_t smem_u32(const void* p) {
    uint32_t a;
    asm("{ .reg .u64 t; cvta.to.shared.u64 t, %1; cvt.u32.u64 %0, t; }"
        : "=r"(a) : "l"(p));
    return a;
}

__device__ __forceinline__ void mma16816(float* d, const uint32_t* a, const uint32_t* b) {
    asm volatile(
        "mma.sync.aligned.m16n8k16.row.col.f32.bf16.bf16.f32 "
        "{%0,%1,%2,%3}, {%4,%5,%6,%7}, {%8,%9}, {%0,%1,%2,%3};"
        : "+f"(d[0]), "+f"(d[1]), "+f"(d[2]), "+f"(d[3])
        : "r"(a[0]), "r"(a[1]), "r"(a[2]), "r"(a[3]), "r"(b[0]), "r"(b[1]));
}

#define LDSM_X4(r, addr) \
    asm volatile("ldmatrix.sync.aligned.m8n8.x4.shared.b16 {%0,%1,%2,%3}, [%4];" \
                 : "=r"((r)[0]), "=r"((r)[1]), "=r"((r)[2]), "=r"((r)[3]) : "r"(addr))
#define LDSM_X2(r, addr) \
    asm volatile("ldmatrix.sync.aligned.m8n8.x2.shared.b16 {%0,%1}, [%2];" \
                 : "=r"((r)[0]), "=r"((r)[1]) : "r"(addr))

#define CP_ASYNC(dst, src) \
    asm volatile("cp.async.cg.shared.global [%0], [%1], 16;" \
                 :: "r"(dst), "l"(src) : "memory")
#define CP_COMMIT() asm volatile("cp.async.commit_group;" ::: "memory")
#define CP_WAIT1()  asm volatile("cp.async.wait_group 1;" ::: "memory")

__device__ __forceinline__ uint32_t pack_bf16(float a, float b) {
    __nv_bfloat16 ha = __float2bfloat16(a);
    __nv_bfloat16 hb = __float2bfloat16(b);
    return (uint32_t)__bfloat16_as_ushort(ha) |
           ((uint32_t)__bfloat16_as_ushort(hb) << 16);
}

// =================================================================
// split: fp32 -> bf16 hi + bf16 lo (residual)
// =================================================================
__global__ __launch_bounds__(256)
void split_bf16(const float* __restrict__ in,
                __nv_bfloat16* __restrict__ hi, __nv_bfloat16* __restrict__ lo,
                int n)
{
    const int i = (blockIdx.x * 256 + threadIdx.x) * 4;
    if (i >= n) return;
    float4 f4 = *(const float4*)(in + i);
    float f[4] = {f4.x, f4.y, f4.z, f4.w};
    uint16_t h[4], l[4];
#pragma unroll
    for (int j = 0; j < 4; j++) {
        __nv_bfloat16 hb = __float2bfloat16(f[j]);
        __nv_bfloat16 lb = __float2bfloat16(f[j] - __bfloat162float(hb));
        h[j] = __bfloat16_as_ushort(hb);
        l[j] = __bfloat16_as_ushort(lb);
    }
    *(uint2*)(hi + i) = make_uint2((uint32_t)h[0] | ((uint32_t)h[1] << 16),
                                   (uint32_t)h[2] | ((uint32_t)h[3] << 16));
    *(uint2*)(lo + i) = make_uint2((uint32_t)l[0] | ((uint32_t)l[1] << 16),
                                   (uint32_t)l[2] | ((uint32_t)l[3] << 16));
}

// =================================================================
// mma.sync bf16x3 GEMM (pre-split, cp.async double buffer, ldmatrix;
// B fragments fetched with x4 ldmatrix). Unchanged from R11 winner.
// =================================================================
#define SROW 20
#define ARR_W (128 * SROW)
#define BUF_W (4 * ARR_W)
#define GEMM_SMEM (2 * BUF_W * 4)

__global__ __launch_bounds__(256, 2)
void mma_gemm_pre(const __nv_bfloat16* __restrict__ Ahg,
                  const __nv_bfloat16* __restrict__ Alg,
                  const __nv_bfloat16* __restrict__ Bhg,
                  const __nv_bfloat16* __restrict__ Blg,
                  float* __restrict__ C, int M, int N, int K)
{
    extern __shared__ uint32_t sw[];
    const uint32_t sbase = smem_u32(sw);

    const int tid = threadIdx.x;
    const int wid = tid >> 5;
    const int lane = tid & 31;
    const int g = lane >> 2;
    const int tig = lane & 3;
    const int wm = (wid & 1) * 64;
    const int wn = (wid >> 1) * 32;

    const int bm = blockIdx.y * 128;
    const int bn = blockIdx.x * 128;

    const int s0 = tid * 2;
    const int lrow0 = s0 >> 2, lseg0 = s0 & 3;
    const int lrow1 = (s0 + 1) >> 2, lseg1 = (s0 + 1) & 3;

    const uint32_t a16 = ((uint32_t)((wm + (lane & 15)) * SROW + (lane >> 4) * 4)) * 4;
    const uint32_t b8q = ((uint32_t)((wn + ((lane >> 4) << 3) + (lane & 7)) * SROW +
                                     ((lane >> 3) & 1) * 4)) * 4;

    float acc[4][4][4];
#pragma unroll
    for (int mt = 0; mt < 4; mt++)
#pragma unroll
        for (int nt = 0; nt < 4; nt++)
#pragma unroll
            for (int r = 0; r < 4; r++) acc[mt][nt][r] = 0.0f;

    const int nch = K >> 5;

    auto issue = [&](int ci, int buf) {
        const int kc = ci << 5;
        const uint32_t bb = sbase + buf * (BUF_W * 4);
#pragma unroll
        for (int j = 0; j < 2; j++) {
            const int row = j ? lrow1 : lrow0;
            const int seg = j ? lseg1 : lseg0;
            const size_t goff = (size_t)(bm + row) * K + kc + seg * 8;
            const size_t goffB = (size_t)(bn + row) * K + kc + seg * 8;
            const uint32_t soff = (row * SROW + seg * 4) * 4;
            CP_ASYNC(bb + 0 * ARR_W * 4 + soff, Ahg + goff);
            CP_ASYNC(bb + 1 * ARR_W * 4 + soff, Alg + goff);
            CP_ASYNC(bb + 2 * ARR_W * 4 + soff, Bhg + goffB);
            CP_ASYNC(bb + 3 * ARR_W * 4 + soff, Blg + goffB);
        }
    };

    issue(0, 0); CP_COMMIT();
    issue(1, 1); CP_COMMIT();

    for (int ci = 0; ci < nch; ci++) {
        const int buf = ci & 1;
        CP_WAIT1();
        __syncthreads();

        const uint32_t Ah_b = sbase + buf * (BUF_W * 4);
        const uint32_t Al_b = Ah_b + ARR_W * 4;
        const uint32_t Bh_b = Ah_b + 2 * ARR_W * 4;
        const uint32_t Bl_b = Ah_b + 3 * ARR_W * 4;

#pragma unroll
        for (int ks = 0; ks < 2; ks++) {
            const uint32_t kwb = ks * 32;
            uint32_t bhf[4][2], blf[4][2];
#pragma unroll
            for (int ntp = 0; ntp < 2; ntp++) {
                uint32_t q[4];
                LDSM_X4(q, Bh_b + b8q + ntp * (16 * SROW * 4) + kwb);
                bhf[2 * ntp][0] = q[0]; bhf[2 * ntp][1] = q[1];
                bhf[2 * ntp + 1][0] = q[2]; bhf[2 * ntp + 1][1] = q[3];
                LDSM_X4(q, Bl_b + b8q + ntp * (16 * SROW * 4) + kwb);
                blf[2 * ntp][0] = q[0]; blf[2 * ntp][1] = q[1];
                blf[2 * ntp + 1][0] = q[2]; blf[2 * ntp + 1][1] = q[3];
            }
#pragma unroll
            for (int mt = 0; mt < 4; mt++) {
                uint32_t ah[4], al[4];
                LDSM_X4(ah, Ah_b + a16 + mt * (16 * SROW * 4) + kwb);
                LDSM_X4(al, Al_b + a16 + mt * (16 * SROW * 4) + kwb);
#pragma unroll
                for (int nt = 0; nt < 4; nt++) {
                    mma16816(acc[mt][nt], ah, bhf[nt]);
                    mma16816(acc[mt][nt], ah, blf[nt]);
                    mma16816(acc[mt][nt], al, bhf[nt]);
                }
            }
        }
        __syncthreads();
        if (ci + 2 < nch) issue(ci + 2, buf);
        CP_COMMIT();
    }

#pragma unroll
    for (int mt = 0; mt < 4; mt++) {
        const int r0 = bm + wm + mt * 16 + g;
#pragma unroll
        for (int nt = 0; nt < 4; nt++) {
            const int col = bn + wn + nt * 8 + tig * 2;
            *(float2*)&C[(size_t)r0 * N + col] =
                make_float2(acc[mt][nt][0], acc[mt][nt][1]);
            *(float2*)&C[(size_t)(r0 + 8) * N + col] =
                make_float2(acc[mt][nt][2], acc[mt][nt][3]);
        }
    }
}

// =================================================================
// Post-process: v-mix, rmsnorm, rotary; q pre-scaled by ATTN_SCALE;
// outputs bf16 hi/lo q,k,v in (B*H, T, D) layout.
// =================================================================
__device__ __forceinline__ void split_store(__nv_bfloat16* H, __nv_bfloat16* L,
                                            size_t o, float f) {
    __nv_bfloat16 hb = __float2bfloat16(f);
    H[o] = hb;
    L[o] = __float2bfloat16(f - __bfloat162float(hb));
}

__global__ __launch_bounds__(256)
void postproc(const float* __restrict__ qkv, const float* __restrict__ ve,
              const float* __restrict__ lambdas,
              __nv_bfloat16* __restrict__ qh, __nv_bfloat16* __restrict__ ql,
              __nv_bfloat16* __restrict__ kh, __nv_bfloat16* __restrict__ kl,
              __nv_bfloat16* __restrict__ vh, __nv_bfloat16* __restrict__ vl)
{
    const int pair = blockIdx.x * 8 + (threadIdx.x >> 5);
    const int l = threadIdx.x & 31;
    const int m = pair >> 4;
    const int h = pair & 15;
    const int t = m & (TT - 1);
    const int b = m >> 11;

    const float* row = qkv + (size_t)m * N_QKV + h * DD;
    float q0 = row[l],          q1 = row[l + 32];
    float k0 = row[CC + l],     k1 = row[CC + l + 32];
    float v0 = row[2 * CC + l], v1 = row[2 * CC + l + 32];

    const float lam0 = lambdas[0], lam1 = lambdas[1];
    const float* verow = ve + (size_t)m * CC + h * DD;
    v0 = lam0 * v0 + lam1 * verow[l];
    v1 = lam0 * v1 + lam1 * verow[l + 32];

    float sq = q0 * q0 + q1 * q1;
    float sk = k0 * k0 + k1 * k1;
#pragma unroll
    for (int o = 16; o; o >>= 1) {
        sq += __shfl_xor_sync(0xffffffffu, sq, o);
        sk += __shfl_xor_sync(0xffffffffu, sk, o);
    }
    float rq = 1.0f / sqrtf(sq * (1.0f / 64.0f) + RMS_EPS);
    float rk = 1.0f / sqrtf(sk * (1.0f / 64.0f) + RMS_EPS);
    q0 *= rq; q1 *= rq;
    k0 *= rk; k1 *= rk;

    float ang = (l < 16) ? (float)exp2(-(10.0 / 15.0) * (double)l) : 0.0f;
    float th = (float)t * ang;
    float s, c;
    sincosf(th, &s, &c);
    float qa = (q0 * c + q1 * s) * ATTN_SCALE;
    float qb_ = (q1 * c - q0 * s) * ATTN_SCALE;
    float ka = k0 * c + k1 * s;
    float kb_ = k1 * c - k0 * s;

    size_t o = ((size_t)(b * HH + h) * TT + t) * DD + l;
    split_store(qh, ql, o,      qa);
    split_store(qh, ql, o + 32, qb_);
    split_store(kh, kl, o,      ka);
    split_store(kh, kl, o + 32, kb_);
    split_store(vh, vl, o,      v0);
    split_store(vh, vl, o + 32, v1);
}

// =================================================================
// V transpose: (B*H, T, D) -> (B*H, D, T), both hi and lo.
// =================================================================
__global__ __launch_bounds__(256)
void transpose_v(const __nv_bfloat16* __restrict__ vh,
                 const __nv_bfloat16* __restrict__ vl,
                 __nv_bfloat16* __restrict__ vth,
                 __nv_bfloat16* __restrict__ vtl)
{
    __shared__ uint16_t th[64][65], tl[64][65];
    const int bh = blockIdx.y, tb = blockIdx.x;
    const int r = threadIdx.x >> 2;
    const int cs = (threadIdx.x & 3) * 16;

    const size_t src = ((size_t)bh * TT + tb * 64 + r) * DD + cs;
    const uint32_t* ph = (const uint32_t*)(vh + src);
    const uint32_t* pl = (const uint32_t*)(vl + src);
#pragma unroll
    for (int j = 0; j < 8; j++) {
        uint32_t wh_ = ph[j], wl_ = pl[j];
        th[r][cs + 2 * j] = (uint16_t)(wh_ & 0xffff);
        th[r][cs + 2 * j + 1] = (uint16_t)(wh_ >> 16);
        tl[r][cs + 2 * j] = (uint16_t)(wl_ & 0xffff);
        tl[r][cs + 2 * j + 1] = (uint16_t)(wl_ >> 16);
    }
    __syncthreads();
    const size_t dst = ((size_t)bh * DD + r) * TT + tb * 64 + cs;
    uint32_t* oh = (uint32_t*)(vth + dst);
    uint32_t* ol = (uint32_t*)(vtl + dst);
#pragma unroll
    for (int j = 0; j < 8; j++) {
        oh[j] = (uint32_t)th[cs + 2 * j][r] | ((uint32_t)th[cs + 2 * j + 1][r] << 16);
        ol[j] = (uint32_t)tl[cs + 2 * j][r] | ((uint32_t)tl[cs + 2 * j + 1][r] << 16);
    }
}

// =================================================================
// Tensor-core flash attention (causal, no-max softmax, bf16x3),
// register-resident P (FA2-style): each warp owns 16 full rows.
// BQ=128, BKV=64, 256 threads, 2 CTAs/SM (110.6 KB smem).
// Smem words: QH 0 (4608), QL 4608, KV 9216 (2 bufs x 4 arr x 2304).
// =================================================================
#define FL_SROW 36
#define FLQ_H 0
#define FLQ_L 4608
#define FLKV 9216
#define FL_SMEM (27648 * 4)   // 110592 B

__global__ __launch_bounds__(256, 2)
void flash_mma(const __nv_bfloat16* __restrict__ qh, const __nv_bfloat16* __restrict__ ql,
               const __nv_bfloat16* __restrict__ kh, const __nv_bfloat16* __restrict__ kl,
               const __nv_bfloat16* __restrict__ vth, const __nv_bfloat16* __restrict__ vtl,
               __nv_bfloat16* __restrict__ yh, __nv_bfloat16* __restrict__ yl)
{
    extern __shared__ uint32_t sw[];
    const uint32_t sb = smem_u32(sw);
    const int tid = threadIdx.x;
    const int wid = tid >> 5;
    const int lane = tid & 31;
    const int g = lane >> 2;
    const int tig = lane & 3;
    const int bh = blockIdx.y;
    const int qb = (int)gridDim.x - 1 - (int)blockIdx.x;   // heavy first

    const int wm = wid * 16;    // this warp's 16 rows of the 128-row Q tile

    // A-frag offset (16 rows x 2 k-halves), B-frag x4 offset (2 nt x 2 k-halves)
    const uint32_t a16 = ((uint32_t)((lane & 15) * FL_SROW + (lane >> 4) * 4)) * 4;
    const uint32_t b8q = ((uint32_t)((((lane >> 4) << 3) + (lane & 7)) * FL_SROW +
                                     ((lane >> 3) & 1) * 4)) * 4;

    const size_t base = (size_t)bh * TT * DD;

    // ---- Q tile load (cp.async): 2 arrays x 128 rows ----
    {
        const int arr = tid >> 7;
        const int row = tid & 127;
        const __nv_bfloat16* src = (arr ? ql : qh) + base + ((size_t)(qb * 128 + row)) * 64;
        const uint32_t dst = sb + ((arr ? FLQ_L : FLQ_H) + row * FL_SROW) * 4;
#pragma unroll
        for (int s = 0; s < 8; s++) CP_ASYNC(dst + s * 16, src + s * 8);
    }

    // KV loader mapping: 4 arrays x 64 rows
    const int kvarr = tid >> 6;          // 0:Kh 1:Kl 2:Vth 3:Vtl
    const int kvrow = tid & 63;
    const bool kvisV = kvarr >= 2;
    const __nv_bfloat16* kvbase =
        (kvarr == 0) ? (kh + base) : (kvarr == 1) ? (kl + base)
        : (kvarr == 2) ? (vth + base) : (vtl + base);
    const uint32_t kvdst0 = sb + (FLKV + kvarr * 2304 + kvrow * FL_SROW) * 4;

    auto issueKV = [&](int kb, int buf) {
        const __nv_bfloat16* src = kvisV
            ? (kvbase + (size_t)kvrow * TT + kb * 64)
            : (kvbase + ((size_t)(kb * 64 + kvrow)) * 64);
        const uint32_t dst = kvdst0 + buf * 9216 * 4;
#pragma unroll
        for (int s = 0; s < 8; s++) CP_ASYNC(dst + s * 16, src + s * 8);
    };

    const int nkb = 2 * qb + 2;
    issueKV(0, 0); CP_COMMIT();          // group: Q + KV0
    if (nkb > 1) issueKV(1, 1);
    CP_COMMIT();
    CP_WAIT1();
    __syncthreads();

    float O[8][4];
    float lp[2] = {0.0f, 0.0f};
#pragma unroll
    for (int nt = 0; nt < 8; nt++)
#pragma unroll
        for (int r = 0; r < 4; r++) O[nt][r] = 0.0f;

    for (int kb = 0; kb < nkb; kb++) {
        const int buf = kb & 1;
        const uint32_t Khb = sb + (FLKV + buf * 9216) * 4;
        const uint32_t Klb = Khb + 2304 * 4;
        const uint32_t Vhb = Khb + 4608 * 4;
        const uint32_t Vlb = Khb + 6912 * 4;

        // ---- S = Q K^T (bf16x3): 16 rows x 64 cols per warp ----
        float S[8][4];
#pragma unroll
        for (int nt = 0; nt < 8; nt++)
#pragma unroll
            for (int r = 0; r < 4; r++) S[nt][r] = 0.0f;

#pragma unroll
        for (int ks = 0; ks < 4; ks++) {
            const uint32_t kwb = ks * 32;
            uint32_t ah[4], al[4];
            LDSM_X4(ah, sb + FLQ_H * 4 + a16 + wm * (FL_SROW * 4) + kwb);
            LDSM_X4(al, sb + FLQ_L * 4 + a16 + wm * (FL_SROW * 4) + kwb);
#pragma unroll
            for (int ntp = 0; ntp < 4; ntp++) {
                uint32_t qk[4], qkl[4];
                LDSM_X4(qk, Khb + b8q + ntp * (16 * FL_SROW * 4) + kwb);
                LDSM_X4(qkl, Klb + b8q + ntp * (16 * FL_SROW * 4) + kwb);
                uint32_t b0[2] = {qk[0], qk[1]}, b1[2] = {qk[2], qk[3]};
                uint32_t c0[2] = {qkl[0], qkl[1]}, c1[2] = {qkl[2], qkl[3]};
                mma16816(S[2 * ntp], ah, b0);
                mma16816(S[2 * ntp], ah, c0);
                mma16816(S[2 * ntp], al, b0);
                mma16816(S[2 * ntp + 1], ah, b1);
                mma16816(S[2 * ntp + 1], ah, c1);
                mma16816(S[2 * ntp + 1], al, b1);
            }
        }

        // ---- exp (no max), row sums, pack P hi/lo into registers ----
        const bool diag = (kb >= 2 * qb);
        uint32_t Ph[8][2], Pl[8][2];
#pragma unroll
        for (int nt = 0; nt < 8; nt++) {
            const int c0i = kb * 64 + nt * 8 + tig * 2;
#pragma unroll
            for (int h2 = 0; h2 < 2; h2++) {
                const int grow = qb * 128 + wm + g + h2 * 8;
                float s0 = S[nt][h2 * 2 + 0];
                float s1 = S[nt][h2 * 2 + 1];
                float p0 = (diag && (c0i > grow)) ? 0.0f : __expf(s0);
                float p1 = (diag && (c0i + 1 > grow)) ? 0.0f : __expf(s1);
                lp[h2] += p0 + p1;
                __nv_bfloat16 hb0 = __float2bfloat16(p0);
                __nv_bfloat16 hb1 = __float2bfloat16(p1);
                Ph[nt][h2] = (uint32_t)__bfloat16_as_ushort(hb0) |
                             ((uint32_t)__bfloat16_as_ushort(hb1) << 16);
                Pl[nt][h2] = pack_bf16(p0 - __bfloat162float(hb0),
                                       p1 - __bfloat162float(hb1));
            }
        }

        // ---- O += P V (bf16x3), P from registers ----
#pragma unroll
        for (int ks = 0; ks < 4; ks++) {
            const uint32_t kwb = ks * 32;
            uint32_t aph[4] = {Ph[2 * ks][0], Ph[2 * ks][1],
                               Ph[2 * ks + 1][0], Ph[2 * ks + 1][1]};
            uint32_t apl[4] = {Pl[2 * ks][0], Pl[2 * ks][1],
                               Pl[2 * ks + 1][0], Pl[2 * ks + 1][1]};
#pragma unroll
            for (int ntp = 0; ntp < 4; ntp++) {
                uint32_t qv[4], qvl[4];
                LDSM_X4(qv, Vhb + b8q + ntp * (16 * FL_SROW * 4) + kwb);
                LDSM_X4(qvl, Vlb + b8q + ntp * (16 * FL_SROW * 4) + kwb);
                uint32_t b0[2] = {qv[0], qv[1]}, b1[2] = {qv[2], qv[3]};
                uint32_t c0[2] = {qvl[0], qvl[1]}, c1[2] = {qvl[2], qvl[3]};
                mma16816(O[2 * ntp], aph, b0);
                mma16816(O[2 * ntp], aph, c0);
                mma16816(O[2 * ntp], apl, b0);
                mma16816(O[2 * ntp + 1], aph, b1);
                mma16816(O[2 * ntp + 1], aph, c1);
                mma16816(O[2 * ntp + 1], apl, b1);
            }
        }
        __syncthreads();                 // all warps done reading buf
        if (kb + 2 < nkb) issueKV(kb + 2, buf);
        CP_COMMIT();
        CP_WAIT1();                      // tile kb+1 ready
        __syncthreads();
    }

    // ---- row-sum reduce (warp-local: rows owned by this warp only) ----
#pragma unroll
    for (int i = 0; i < 2; i++) {
        lp[i] += __shfl_xor_sync(0xffffffffu, lp[i], 1);
        lp[i] += __shfl_xor_sync(0xffffffffu, lp[i], 2);
    }

    // ---- epilogue: O/l -> y bf16 hi/lo, (M, C) layout ----
    const int b = bh >> 4;
    const int h = bh & 15;
#pragma unroll
    for (int h2 = 0; h2 < 2; h2++) {
        const float linv = 1.0f / lp[h2];
        const int t = qb * 128 + wm + g + h2 * 8;
        const size_t rowoff = ((size_t)(b * TT + t)) * CC + h * 64;
#pragma unroll
        for (int nt = 0; nt < 8; nt++) {
            float o0 = O[nt][h2 * 2 + 0] * linv;
            float o1 = O[nt][h2 * 2 + 1] * linv;
            __nv_bfloat16 hb0 = __float2bfloat16(o0);
            __nv_bfloat16 hb1 = __float2bfloat16(o1);
            const size_t col = rowoff + nt * 8 + tig * 2;
            *(uint32_t*)(yh + col) = (uint32_t)__bfloat16_as_ushort(hb0) |
                                     ((uint32_t)__bfloat16_as_ushort(hb1) << 16);
            *(uint32_t*)(yl + col) = pack_bf16(o0 - __bfloat162float(hb0),
                                               o1 - __bfloat162float(hb1));
        }
    }
}

// =================================================================
// launch
// =================================================================
extern "C" void kernel_launch(void* const* d_in, const int* in_sizes, int n_in,
                              void* d_out, int out_size)
{
    const float* x        = (const float*)d_in[0];
    const float* ve       = (const float*)d_in[1];
    const float* qkv_w    = (const float*)d_in[2];
    const float* lambdas  = (const float*)d_in[3];
    const float* c_proj_w = (const float*)d_in[4];
    float* out = (float*)d_out;

    float* qkv_p;
    cudaGetSymbolAddress((void**)&qkv_p, g_qkv);
    __nv_bfloat16 *xh, *xl, *wh, *wl, *yh, *yl, *ph, *pl;
    cudaGetSymbolAddress((void**)&xh, g_xh); cudaGetSymbolAddress((void**)&xl, g_xl);
    cudaGetSymbolAddress((void**)&wh, g_wh); cudaGetSymbolAddress((void**)&wl, g_wl);
    cudaGetSymbolAddress((void**)&yh, g_yh); cudaGetSymbolAddress((void**)&yl, g_yl);
    cudaGetSymbolAddress((void**)&ph, g_ph); cudaGetSymbolAddress((void**)&pl, g_pl);
    __nv_bfloat16 *qh, *ql, *kh, *kl, *vh, *vl, *vth, *vtl;
    cudaGetSymbolAddress((void**)&qh, g_qh); cudaGetSymbolAddress((void**)&ql, g_ql);
    cudaGetSymbolAddress((void**)&kh, g_kh); cudaGetSymbolAddress((void**)&kl, g_kl);
    cudaGetSymbolAddress((void**)&vh, g_vh); cudaGetSymbolAddress((void**)&vl, g_vl);
    cudaGetSymbolAddress((void**)&vth, g_vth); cudaGetSymbolAddress((void**)&vtl, g_vtl);

    cudaFuncSetAttribute(mma_gemm_pre, cudaFuncAttributeMaxDynamicSharedMemorySize, GEMM_SMEM);
    cudaFuncSetAttribute(flash_mma, cudaFuncAttributeMaxDynamicSharedMemorySize, FL_SMEM);

    // 0) pre-split fp32 -> bf16 hi/lo
    split_bf16<<<(MM * CC) / 1024, 256>>>(x, xh, xl, MM * CC);
    split_bf16<<<(N_QKV * CC) / 1024, 256>>>(qkv_w, wh, wl, N_QKV * CC);

    // 1) qkv = x @ qkv_w^T
    mma_gemm_pre<<<dim3(N_QKV / 128, MM / 128), 256, GEMM_SMEM>>>(
        xh, xl, wh, wl, qkv_p, MM, N_QKV, CC);

    // 2) v-mix + rmsnorm + rotary -> bf16 hi/lo (q scaled by ATTN_SCALE)
    postproc<<<(MM * HH) / 8, 256>>>(qkv_p, ve, lambdas, qh, ql, kh, kl, vh, vl);

    // 2b) transpose V to (B*H, D, T)
    transpose_v<<<dim3(TT / 64, BB * HH), 256>>>(vh, vl, vth, vtl);

    // 3) tensor-core causal flash attention -> y bf16 hi/lo
    flash_mma<<<dim3(TT / 128, BB * HH), 256, FL_SMEM>>>(
        qh, ql, kh, kl, vth, vtl, yh, yl);

    // 4) out = y @ c_proj_w^T
    split_bf16<<<(CC * CC) / 1024, 256>>>(c_proj_w, ph, pl, CC * CC);
    mma_gemm_pre<<<dim3(CC / 128, MM / 128), 256, GEMM_SMEM>>>(
        yh, yl, ph, pl, out, MM, CC, CC);
}

// round 13
// speedup vs baseline: 1.1317x; 1.0278x over previous
#include <cuda_runtime.h>
#include <cuda_bf16.h>
#include <math.h>
#include <stdint.h>

// Problem constants
#define BB 4
#define TT 2048
#define CC 1024
#define HH 16
#define DD 64
#define MM (BB * TT)         // 8192
#define N_QKV (3 * CC)       // 3072
#define ATTN_SCALE 0.12f
#define RMS_EPS 1e-6f
#define LOG2E 1.4426950408889634f

// ---------------- device scratch (allocation-free) ----------------
__device__ float g_qkv[(size_t)MM * N_QKV];          // (M, 3C)
__device__ __nv_bfloat16 g_xh[(size_t)MM * CC],     g_xl[(size_t)MM * CC];
__device__ __nv_bfloat16 g_wh[(size_t)N_QKV * CC],  g_wl[(size_t)N_QKV * CC];
__device__ __nv_bfloat16 g_yh[(size_t)MM * CC],     g_yl[(size_t)MM * CC];
__device__ __nv_bfloat16 g_ph[(size_t)CC * CC],     g_pl[(size_t)CC * CC];
#define AHD ((size_t)BB * HH * TT * DD)
__device__ __nv_bfloat16 g_qh[AHD], g_ql[AHD];
__device__ __nv_bfloat16 g_kh[AHD], g_kl[AHD];
__device__ __nv_bfloat16 g_vh[AHD], g_vl[AHD];
__device__ __nv_bfloat16 g_vth[AHD], g_vtl[AHD];

// =================================================================
// common helpers
// =================================================================
__device__ __forceinline__ uint32_t smem_u32(const void* p) {
    uint32_t a;
    asm("{ .reg .u64 t; cvta.to.shared.u64 t, %1; cvt.u32.u64 %0, t; }"
        : "=r"(a) : "l"(p));
    return a;
}

__device__ __forceinline__ void mma16816(float* d, const uint32_t* a, const uint32_t* b) {
    asm volatile(
        "mma.sync.aligned.m16n8k16.row.col.f32.bf16.bf16.f32 "
        "{%0,%1,%2,%3}, {%4,%5,%6,%7}, {%8,%9}, {%0,%1,%2,%3};"
        : "+f"(d[0]), "+f"(d[1]), "+f"(d[2]), "+f"(d[3])
        : "r"(a[0]), "r"(a[1]), "r"(a[2]), "r"(a[3]), "r"(b[0]), "r"(b[1]));
}

#define LDSM_X4(r, addr) \
    asm volatile("ldmatrix.sync.aligned.m8n8.x4.shared.b16 {%0,%1,%2,%3}, [%4];" \
                 : "=r"((r)[0]), "=r"((r)[1]), "=r"((r)[2]), "=r"((r)[3]) : "r"(addr))

#define CP_ASYNC(dst, src) \
    asm volatile("cp.async.cg.shared.global [%0], [%1], 16;" \
                 :: "r"(dst), "l"(src) : "memory")
#define CP_COMMIT() asm volatile("cp.async.commit_group;" ::: "memory")
#define CP_WAIT1()  asm volatile("cp.async.wait_group 1;" ::: "memory")

__device__ __forceinline__ uint32_t pack_bf16(float a, float b) {
    __nv_bfloat16 ha = __float2bfloat16(a);
    __nv_bfloat16 hb = __float2bfloat16(b);
    return (uint32_t)__bfloat16_as_ushort(ha) |
           ((uint32_t)__bfloat16_as_ushort(hb) << 16);
}

__device__ __forceinline__ float ex2f(float x) {
    float y;
    asm("ex2.approx.f32 %0, %1;" : "=f"(y) : "f"(x));
    return y;
}

// =================================================================
// split3: one launch splits x, qkv_w, c_proj_w fp32 -> bf16 hi/lo
// =================================================================
__device__ __forceinline__ void split4(const float* __restrict__ in, int i,
                                       __nv_bfloat16* __restrict__ hi,
                                       __nv_bfloat16* __restrict__ lo)
{
    float4 f4 = *(const float4*)(in + i);
    float f[4] = {f4.x, f4.y, f4.z, f4.w};
    uint16_t h[4], l[4];
#pragma unroll
    for (int j = 0; j < 4; j++) {
        __nv_bfloat16 hb = __float2bfloat16(f[j]);
        __nv_bfloat16 lb = __float2bfloat16(f[j] - __bfloat162float(hb));
        h[j] = __bfloat16_as_ushort(hb);
        l[j] = __bfloat16_as_ushort(lb);
    }
    *(uint2*)(hi + i) = make_uint2((uint32_t)h[0] | ((uint32_t)h[1] << 16),
                                   (uint32_t)h[2] | ((uint32_t)h[3] << 16));
    *(uint2*)(lo + i) = make_uint2((uint32_t)l[0] | ((uint32_t)l[1] << 16),
                                   (uint32_t)l[2] | ((uint32_t)l[3] << 16));
}

#define N_X (MM * CC)
#define N_W (N_QKV * CC)
#define N_P (CC * CC)

__global__ __launch_bounds__(256)
void split3(const float* __restrict__ x,
            __nv_bfloat16* __restrict__ xh, __nv_bfloat16* __restrict__ xl,
            const float* __restrict__ w,
            __nv_bfloat16* __restrict__ wh, __nv_bfloat16* __restrict__ wl,
            const float* __restrict__ p,
            __nv_bfloat16* __restrict__ ph, __nv_bfloat16* __restrict__ pl)
{
    const int i = (blockIdx.x * 256 + threadIdx.x) * 4;
    if (i < N_X) {
        split4(x, i, xh, xl);
    } else if (i < N_X + N_W) {
        split4(w, i - N_X, wh, wl);
    } else {
        split4(p, i - N_X - N_W, ph, pl);
    }
}

// =================================================================
// mma.sync bf16x3 GEMM (pre-split, cp.async double buffer, ldmatrix;
// B fragments fetched with x4 ldmatrix). Unchanged from R11 winner.
// =================================================================
#define SROW 20
#define ARR_W (128 * SROW)
#define BUF_W (4 * ARR_W)
#define GEMM_SMEM (2 * BUF_W * 4)

__global__ __launch_bounds__(256, 2)
void mma_gemm_pre(const __nv_bfloat16* __restrict__ Ahg,
                  const __nv_bfloat16* __restrict__ Alg,
                  const __nv_bfloat16* __restrict__ Bhg,
                  const __nv_bfloat16* __restrict__ Blg,
                  float* __restrict__ C, int M, int N, int K)
{
    extern __shared__ uint32_t sw[];
    const uint32_t sbase = smem_u32(sw);

    const int tid = threadIdx.x;
    const int wid = tid >> 5;
    const int lane = tid & 31;
    const int g = lane >> 2;
    const int tig = lane & 3;
    const int wm = (wid & 1) * 64;
    const int wn = (wid >> 1) * 32;

    const int bm = blockIdx.y * 128;
    const int bn = blockIdx.x * 128;

    const int s0 = tid * 2;
    const int lrow0 = s0 >> 2, lseg0 = s0 & 3;
    const int lrow1 = (s0 + 1) >> 2, lseg1 = (s0 + 1) & 3;

    const uint32_t a16 = ((uint32_t)((wm + (lane & 15)) * SROW + (lane >> 4) * 4)) * 4;
    const uint32_t b8q = ((uint32_t)((wn + ((lane >> 4) << 3) + (lane & 7)) * SROW +
                                     ((lane >> 3) & 1) * 4)) * 4;

    float acc[4][4][4];
#pragma unroll
    for (int mt = 0; mt < 4; mt++)
#pragma unroll
        for (int nt = 0; nt < 4; nt++)
#pragma unroll
            for (int r = 0; r < 4; r++) acc[mt][nt][r] = 0.0f;

    const int nch = K >> 5;

    auto issue = [&](int ci, int buf) {
        const int kc = ci << 5;
        const uint32_t bb = sbase + buf * (BUF_W * 4);
#pragma unroll
        for (int j = 0; j < 2; j++) {
            const int row = j ? lrow1 : lrow0;
            const int seg = j ? lseg1 : lseg0;
            const size_t goff = (size_t)(bm + row) * K + kc + seg * 8;
            const size_t goffB = (size_t)(bn + row) * K + kc + seg * 8;
            const uint32_t soff = (row * SROW + seg * 4) * 4;
            CP_ASYNC(bb + 0 * ARR_W * 4 + soff, Ahg + goff);
            CP_ASYNC(bb + 1 * ARR_W * 4 + soff, Alg + goff);
            CP_ASYNC(bb + 2 * ARR_W * 4 + soff, Bhg + goffB);
            CP_ASYNC(bb + 3 * ARR_W * 4 + soff, Blg + goffB);
        }
    };

    issue(0, 0); CP_COMMIT();
    issue(1, 1); CP_COMMIT();

    for (int ci = 0; ci < nch; ci++) {
        const int buf = ci & 1;
        CP_WAIT1();
        __syncthreads();

        const uint32_t Ah_b = sbase + buf * (BUF_W * 4);
        const uint32_t Al_b = Ah_b + ARR_W * 4;
        const uint32_t Bh_b = Ah_b + 2 * ARR_W * 4;
        const uint32_t Bl_b = Ah_b + 3 * ARR_W * 4;

#pragma unroll
        for (int ks = 0; ks < 2; ks++) {
            const uint32_t kwb = ks * 32;
            uint32_t bhf[4][2], blf[4][2];
#pragma unroll
            for (int ntp = 0; ntp < 2; ntp++) {
                uint32_t q[4];
                LDSM_X4(q, Bh_b + b8q + ntp * (16 * SROW * 4) + kwb);
                bhf[2 * ntp][0] = q[0]; bhf[2 * ntp][1] = q[1];
                bhf[2 * ntp + 1][0] = q[2]; bhf[2 * ntp + 1][1] = q[3];
                LDSM_X4(q, Bl_b + b8q + ntp * (16 * SROW * 4) + kwb);
                blf[2 * ntp][0] = q[0]; blf[2 * ntp][1] = q[1];
                blf[2 * ntp + 1][0] = q[2]; blf[2 * ntp + 1][1] = q[3];
            }
#pragma unroll
            for (int mt = 0; mt < 4; mt++) {
                uint32_t ah[4], al[4];
                LDSM_X4(ah, Ah_b + a16 + mt * (16 * SROW * 4) + kwb);
                LDSM_X4(al, Al_b + a16 + mt * (16 * SROW * 4) + kwb);
#pragma unroll
                for (int nt = 0; nt < 4; nt++) {
                    mma16816(acc[mt][nt], ah, bhf[nt]);
                    mma16816(acc[mt][nt], ah, blf[nt]);
                    mma16816(acc[mt][nt], al, bhf[nt]);
                }
            }
        }
        __syncthreads();
        if (ci + 2 < nch) issue(ci + 2, buf);
        CP_COMMIT();
    }

#pragma unroll
    for (int mt = 0; mt < 4; mt++) {
        const int r0 = bm + wm + mt * 16 + g;
#pragma unroll
        for (int nt = 0; nt < 4; nt++) {
            const int col = bn + wn + nt * 8 + tig * 2;
            *(float2*)&C[(size_t)r0 * N + col] =
                make_float2(acc[mt][nt][0], acc[mt][nt][1]);
            *(float2*)&C[(size_t)(r0 + 8) * N + col] =
                make_float2(acc[mt][nt][2], acc[mt][nt][3]);
        }
    }
}

// =================================================================
// Post-process: v-mix, rmsnorm, rotary; q pre-scaled by
// ATTN_SCALE*log2(e) (flash uses ex2); bf16 hi/lo out.
// =================================================================
__device__ __forceinline__ void split_store(__nv_bfloat16* H, __nv_bfloat16* L,
                                            size_t o, float f) {
    __nv_bfloat16 hb = __float2bfloat16(f);
    H[o] = hb;
    L[o] = __float2bfloat16(f - __bfloat162float(hb));
}

__global__ __launch_bounds__(256)
void postproc(const float* __restrict__ qkv, const float* __restrict__ ve,
              const float* __restrict__ lambdas,
              __nv_bfloat16* __restrict__ qh, __nv_bfloat16* __restrict__ ql,
              __nv_bfloat16* __restrict__ kh, __nv_bfloat16* __restrict__ kl,
              __nv_bfloat16* __restrict__ vh, __nv_bfloat16* __restrict__ vl)
{
    const int pair = blockIdx.x * 8 + (threadIdx.x >> 5);
    const int l = threadIdx.x & 31;
    const int m = pair >> 4;
    const int h = pair & 15;
    const int t = m & (TT - 1);
    const int b = m >> 11;

    const float* row = qkv + (size_t)m * N_QKV + h * DD;
    float q0 = row[l],          q1 = row[l + 32];
    float k0 = row[CC + l],     k1 = row[CC + l + 32];
    float v0 = row[2 * CC + l], v1 = row[2 * CC + l + 32];

    const float lam0 = lambdas[0], lam1 = lambdas[1];
    const float* verow = ve + (size_t)m * CC + h * DD;
    v0 = lam0 * v0 + lam1 * verow[l];
    v1 = lam0 * v1 + lam1 * verow[l + 32];

    float sq = q0 * q0 + q1 * q1;
    float sk = k0 * k0 + k1 * k1;
#pragma unroll
    for (int o = 16; o; o >>= 1) {
        sq += __shfl_xor_sync(0xffffffffu, sq, o);
        sk += __shfl_xor_sync(0xffffffffu, sk, o);
    }
    float rq = 1.0f / sqrtf(sq * (1.0f / 64.0f) + RMS_EPS);
    float rk = 1.0f / sqrtf(sk * (1.0f / 64.0f) + RMS_EPS);
    q0 *= rq; q1 *= rq;
    k0 *= rk; k1 *= rk;

    float ang = (l < 16) ? (float)exp2(-(10.0 / 15.0) * (double)l) : 0.0f;
    float th = (float)t * ang;
    float s, c;
    sincosf(th, &s, &c);
    const float qs = ATTN_SCALE * LOG2E;
    float qa = (q0 * c + q1 * s) * qs;
    float qb_ = (q1 * c - q0 * s) * qs;
    float ka = k0 * c + k1 * s;
    float kb_ = k1 * c - k0 * s;

    size_t o = ((size_t)(b * HH + h) * TT + t) * DD + l;
    split_store(qh, ql, o,      qa);
    split_store(qh, ql, o + 32, qb_);
    split_store(kh, kl, o,      ka);
    split_store(kh, kl, o + 32, kb_);
    split_store(vh, vl, o,      v0);
    split_store(vh, vl, o + 32, v1);
}

// =================================================================
// V transpose: (B*H, T, D) -> (B*H, D, T), both hi and lo.
// =================================================================
__global__ __launch_bounds__(256)
void transpose_v(const __nv_bfloat16* __restrict__ vh,
                 const __nv_bfloat16* __restrict__ vl,
                 __nv_bfloat16* __restrict__ vth,
                 __nv_bfloat16* __restrict__ vtl)
{
    __shared__ uint16_t th[64][65], tl[64][65];
    const int bh = blockIdx.y, tb = blockIdx.x;
    const int r = threadIdx.x >> 2;
    const int cs = (threadIdx.x & 3) * 16;

    const size_t src = ((size_t)bh * TT + tb * 64 + r) * DD + cs;
    const uint32_t* ph = (const uint32_t*)(vh + src);
    const uint32_t* pl = (const uint32_t*)(vl + src);
#pragma unroll
    for (int j = 0; j < 8; j++) {
        uint32_t wh_ = ph[j], wl_ = pl[j];
        th[r][cs + 2 * j] = (uint16_t)(wh_ & 0xffff);
        th[r][cs + 2 * j + 1] = (uint16_t)(wh_ >> 16);
        tl[r][cs + 2 * j] = (uint16_t)(wl_ & 0xffff);
        tl[r][cs + 2 * j + 1] = (uint16_t)(wl_ >> 16);
    }
    __syncthreads();
    const size_t dst = ((size_t)bh * DD + r) * TT + tb * 64 + cs;
    uint32_t* oh = (uint32_t*)(vth + dst);
    uint32_t* ol = (uint32_t*)(vtl + dst);
#pragma unroll
    for (int j = 0; j < 8; j++) {
        oh[j] = (uint32_t)th[cs + 2 * j][r] | ((uint32_t)th[cs + 2 * j + 1][r] << 16);
        ol[j] = (uint32_t)tl[cs + 2 * j][r] | ((uint32_t)tl[cs + 2 * j + 1][r] << 16);
    }
}

// =================================================================
// Tensor-core flash attention (causal, no-max softmax via ex2,
// bf16x3), register-resident P AND register-cached Q fragments.
// BQ=128, BKV=64, 256 threads, 2 CTAs/SM (110.6 KB smem).
// =================================================================
#define FL_SROW 36
#define FLQ_H 0
#define FLQ_L 4608
#define FLKV 9216
#define FL_SMEM (27648 * 4)   // 110592 B

__global__ __launch_bounds__(256, 2)
void flash_mma(const __nv_bfloat16* __restrict__ qh, const __nv_bfloat16* __restrict__ ql,
               const __nv_bfloat16* __restrict__ kh, const __nv_bfloat16* __restrict__ kl,
               const __nv_bfloat16* __restrict__ vth, const __nv_bfloat16* __restrict__ vtl,
               __nv_bfloat16* __restrict__ yh, __nv_bfloat16* __restrict__ yl)
{
    extern __shared__ uint32_t sw[];
    const uint32_t sb = smem_u32(sw);
    const int tid = threadIdx.x;
    const int wid = tid >> 5;
    const int lane = tid & 31;
    const int g = lane >> 2;
    const int tig = lane & 3;
    const int bh = blockIdx.y;
    const int qb = (int)gridDim.x - 1 - (int)blockIdx.x;   // heavy first

    const int wm = wid * 16;    // this warp's 16 rows of the 128-row Q tile

    const uint32_t a16 = ((uint32_t)((lane & 15) * FL_SROW + (lane >> 4) * 4)) * 4;
    const uint32_t b8q = ((uint32_t)((((lane >> 4) << 3) + (lane & 7)) * FL_SROW +
                                     ((lane >> 3) & 1) * 4)) * 4;

    const size_t base = (size_t)bh * TT * DD;

    // ---- Q tile load (cp.async): 2 arrays x 128 rows ----
    {
        const int arr = tid >> 7;
        const int row = tid & 127;
        const __nv_bfloat16* src = (arr ? ql : qh) + base + ((size_t)(qb * 128 + row)) * 64;
        const uint32_t dst = sb + ((arr ? FLQ_L : FLQ_H) + row * FL_SROW) * 4;
#pragma unroll
        for (int s = 0; s < 8; s++) CP_ASYNC(dst + s * 16, src + s * 8);
    }

    // KV loader mapping: 4 arrays x 64 rows
    const int kvarr = tid >> 6;          // 0:Kh 1:Kl 2:Vth 3:Vtl
    const int kvrow = tid & 63;
    const bool kvisV = kvarr >= 2;
    const __nv_bfloat16* kvbase =
        (kvarr == 0) ? (kh + base) : (kvarr == 1) ? (kl + base)
        : (kvarr == 2) ? (vth + base) : (vtl + base);
    const uint32_t kvdst0 = sb + (FLKV + kvarr * 2304 + kvrow * FL_SROW) * 4;

    auto issueKV = [&](int kb, int buf) {
        const __nv_bfloat16* src = kvisV
            ? (kvbase + (size_t)kvrow * TT + kb * 64)
            : (kvbase + ((size_t)(kb * 64 + kvrow)) * 64);
        const uint32_t dst = kvdst0 + buf * 9216 * 4;
#pragma unroll
        for (int s = 0; s < 8; s++) CP_ASYNC(dst + s * 16, src + s * 8);
    };

    const int nkb = 2 * qb + 2;
    issueKV(0, 0); CP_COMMIT();          // group: Q + KV0
    if (nkb > 1) issueKV(1, 1);
    CP_COMMIT();
    CP_WAIT1();                          // Q + KV0 ready
    __syncthreads();

    // ---- cache Q fragments in registers (CTA-invariant) ----
    uint32_t qfh[4][4], qfl[4][4];
#pragma unroll
    for (int ks = 0; ks < 4; ks++) {
        LDSM_X4(qfh[ks], sb + FLQ_H * 4 + a16 + wm * (FL_SROW * 4) + ks * 32);
        LDSM_X4(qfl[ks], sb + FLQ_L * 4 + a16 + wm * (FL_SROW * 4) + ks * 32);
    }

    float O[8][4];
    float lp[2] = {0.0f, 0.0f};
#pragma unroll
    for (int nt = 0; nt < 8; nt++)
#pragma unroll
        for (int r = 0; r < 4; r++) O[nt][r] = 0.0f;

    for (int kb = 0; kb < nkb; kb++) {
        const int buf = kb & 1;
        const uint32_t Khb = sb + (FLKV + buf * 9216) * 4;
        const uint32_t Klb = Khb + 2304 * 4;
        const uint32_t Vhb = Khb + 4608 * 4;
        const uint32_t Vlb = Khb + 6912 * 4;

        // ---- S = Q K^T (bf16x3): 16 rows x 64 cols per warp ----
        float S[8][4];
#pragma unroll
        for (int nt = 0; nt < 8; nt++)
#pragma unroll
            for (int r = 0; r < 4; r++) S[nt][r] = 0.0f;

#pragma unroll
        for (int ks = 0; ks < 4; ks++) {
            const uint32_t kwb = ks * 32;
#pragma unroll
            for (int ntp = 0; ntp < 4; ntp++) {
                uint32_t qk[4], qkl[4];
                LDSM_X4(qk, Khb + b8q + ntp * (16 * FL_SROW * 4) + kwb);
                LDSM_X4(qkl, Klb + b8q + ntp * (16 * FL_SROW * 4) + kwb);
                uint32_t b0[2] = {qk[0], qk[1]}, b1[2] = {qk[2], qk[3]};
                uint32_t c0[2] = {qkl[0], qkl[1]}, c1[2] = {qkl[2], qkl[3]};
                mma16816(S[2 * ntp], qfh[ks], b0);
                mma16816(S[2 * ntp], qfh[ks], c0);
                mma16816(S[2 * ntp], qfl[ks], b0);
                mma16816(S[2 * ntp + 1], qfh[ks], b1);
                mma16816(S[2 * ntp + 1], qfh[ks], c1);
                mma16816(S[2 * ntp + 1], qfl[ks], b1);
            }
        }

        // ---- PV with fused exp2/pack (P built per-ks from live S) ----
        const bool diag = (kb >= 2 * qb);
#pragma unroll
        for (int ks = 0; ks < 4; ks++) {
            const uint32_t kwb = ks * 32;
            uint32_t aph[4], apl[4];
#pragma unroll
            for (int j = 0; j < 2; j++) {
                const int nt = 2 * ks + j;
                const int c0i = kb * 64 + nt * 8 + tig * 2;
#pragma unroll
                for (int h2 = 0; h2 < 2; h2++) {
                    const int grow = qb * 128 + wm + g + h2 * 8;
                    float s0 = S[nt][h2 * 2 + 0];
                    float s1 = S[nt][h2 * 2 + 1];
                    float p0 = (diag && (c0i > grow)) ? 0.0f : ex2f(s0);
                    float p1 = (diag && (c0i + 1 > grow)) ? 0.0f : ex2f(s1);
                    lp[h2] += p0 + p1;
                    __nv_bfloat16 hb0 = __float2bfloat16(p0);
                    __nv_bfloat16 hb1 = __float2bfloat16(p1);
                    aph[j * 2 + h2] = (uint32_t)__bfloat16_as_ushort(hb0) |
                                      ((uint32_t)__bfloat16_as_ushort(hb1) << 16);
                    apl[j * 2 + h2] = pack_bf16(p0 - __bfloat162float(hb0),
                                                p1 - __bfloat162float(hb1));
                }
            }
#pragma unroll
            for (int ntp = 0; ntp < 4; ntp++) {
                uint32_t qv[4], qvl[4];
                LDSM_X4(qv, Vhb + b8q + ntp * (16 * FL_SROW * 4) + kwb);
                LDSM_X4(qvl, Vlb + b8q + ntp * (16 * FL_SROW * 4) + kwb);
                uint32_t b0[2] = {qv[0], qv[1]}, b1[2] = {qv[2], qv[3]};
                uint32_t c0[2] = {qvl[0], qvl[1]}, c1[2] = {qvl[2], qvl[3]};
                mma16816(O[2 * ntp], aph, b0);
                mma16816(O[2 * ntp], aph, c0);
                mma16816(O[2 * ntp], apl, b0);
                mma16816(O[2 * ntp + 1], aph, b1);
                mma16816(O[2 * ntp + 1], aph, c1);
                mma16816(O[2 * ntp + 1], apl, b1);
            }
        }
        __syncthreads();                 // all warps done reading buf
        if (kb + 2 < nkb) issueKV(kb + 2, buf);
        CP_COMMIT();
        CP_WAIT1();                      // tile kb+1 ready
        __syncthreads();
    }

    // ---- row-sum reduce (warp-local) ----
#pragma unroll
    for (int i = 0; i < 2; i++) {
        lp[i] += __shfl_xor_sync(0xffffffffu, lp[i], 1);
        lp[i] += __shfl_xor_sync(0xffffffffu, lp[i], 2);
    }

    // ---- epilogue: O/l -> y bf16 hi/lo, (M, C) layout ----
    const int b = bh >> 4;
    const int h = bh & 15;
#pragma unroll
    for (int h2 = 0; h2 < 2; h2++) {
        const float linv = 1.0f / lp[h2];
        const int t = qb * 128 + wm + g + h2 * 8;
        const size_t rowoff = ((size_t)(b * TT + t)) * CC + h * 64;
#pragma unroll
        for (int nt = 0; nt < 8; nt++) {
            float o0 = O[nt][h2 * 2 + 0] * linv;
            float o1 = O[nt][h2 * 2 + 1] * linv;
            __nv_bfloat16 hb0 = __float2bfloat16(o0);
            __nv_bfloat16 hb1 = __float2bfloat16(o1);
            const size_t col = rowoff + nt * 8 + tig * 2;
            *(uint32_t*)(yh + col) = (uint32_t)__bfloat16_as_ushort(hb0) |
                                     ((uint32_t)__bfloat16_as_ushort(hb1) << 16);
            *(uint32_t*)(yl + col) = pack_bf16(o0 - __bfloat162float(hb0),
                                               o1 - __bfloat162float(hb1));
        }
    }
}

// =================================================================
// launch
// =================================================================
extern "C" void kernel_launch(void* const* d_in, const int* in_sizes, int n_in,
                              void* d_out, int out_size)
{
    const float* x        = (const float*)d_in[0];
    const float* ve       = (const float*)d_in[1];
    const float* qkv_w    = (const float*)d_in[2];
    const float* lambdas  = (const float*)d_in[3];
    const float* c_proj_w = (const float*)d_in[4];
    float* out = (float*)d_out;

    float* qkv_p;
    cudaGetSymbolAddress((void**)&qkv_p, g_qkv);
    __nv_bfloat16 *xh, *xl, *wh, *wl, *yh, *yl, *ph, *pl;
    cudaGetSymbolAddress((void**)&xh, g_xh); cudaGetSymbolAddress((void**)&xl, g_xl);
    cudaGetSymbolAddress((void**)&wh, g_wh); cudaGetSymbolAddress((void**)&wl, g_wl);
    cudaGetSymbolAddress((void**)&yh, g_yh); cudaGetSymbolAddress((void**)&yl, g_yl);
    cudaGetSymbolAddress((void**)&ph, g_ph); cudaGetSymbolAddress((void**)&pl, g_pl);
    __nv_bfloat16 *qh, *ql, *kh, *kl, *vh, *vl, *vth, *vtl;
    cudaGetSymbolAddress((void**)&qh, g_qh); cudaGetSymbolAddress((void**)&ql, g_ql);
    cudaGetSymbolAddress((void**)&kh, g_kh); cudaGetSymbolAddress((void**)&kl, g_kl);
    cudaGetSymbolAddress((void**)&vh, g_vh); cudaGetSymbolAddress((void**)&vl, g_vl);
    cudaGetSymbolAddress((void**)&vth, g_vth); cudaGetSymbolAddress((void**)&vtl, g_vtl);

    cudaFuncSetAttribute(mma_gemm_pre, cudaFuncAttributeMaxDynamicSharedMemorySize, GEMM_SMEM);
    cudaFuncSetAttribute(flash_mma, cudaFuncAttributeMaxDynamicSharedMemorySize, FL_SMEM);

    // 0) pre-split fp32 -> bf16 hi/lo (x, qkv_w, c_proj_w in one launch)
    split3<<<(N_X + N_W + N_P) / 1024, 256>>>(x, xh, xl, qkv_w, wh, wl,
                                              c_proj_w, ph, pl);

    // 1) qkv = x @ qkv_w^T
    mma_gemm_pre<<<dim3(N_QKV / 128, MM / 128), 256, GEMM_SMEM>>>(
        xh, xl, wh, wl, qkv_p, MM, N_QKV, CC);

    // 2) v-mix + rmsnorm + rotary -> bf16 hi/lo (q scaled by ATTN_SCALE*log2e)
    postproc<<<(MM * HH) / 8, 256>>>(qkv_p, ve, lambdas, qh, ql, kh, kl, vh, vl);

    // 2b) transpose V to (B*H, D, T)
    transpose_v<<<dim3(TT / 64, BB * HH), 256>>>(vh, vl, vth, vtl);

    // 3) tensor-core causal flash attention -> y bf16 hi/lo
    flash_mma<<<dim3(TT / 128, BB * HH), 256, FL_SMEM>>>(
        qh, ql, kh, kl, vth, vtl, yh, yl);

    // 4) out = y @ c_proj_w^T
    mma_gemm_pre<<<dim3(CC / 128, MM / 128), 256, GEMM_SMEM>>>(
        yh, yl, ph, pl, out, MM, CC, CC);
}